// round 13
// baseline (speedup 1.0000x reference)
#include <cuda_runtime.h>
#include <cuda_fp16.h>
#include <math.h>
#include <stdint.h>

// ---------------- problem constants ----------------
#define BB 4
#define NN 4096
#define DD 1024
#define HH 16
#define HD 64
#define MTOT (BB*NN)          // 16384
#define N3D (3*DD)            // 3072
#define NSCALES 11

#define C0 0.4829629131445341f
#define C1 0.8365163037378079f
#define C2 0.2241438680420134f
#define C3 (-0.1294095225512604f)

// ---------------- scratch (device globals; allocation-free) ----------------
__device__ __half g_xh    [(size_t)MTOT * DD];      // 32 MB
__device__ __half g_vh    [(size_t)MTOT * DD];      // 32 MB
__device__ float  g_ksq2  [(size_t)MTOT * HH * 2];  // 2 MB (2 partials/(row,head))
__device__ __half g_gateh [(size_t)MTOT * DD];      // 32 MB
__device__ __half g_fieldh[(size_t)BB*HH*HD*NN];    // [bh][d][n] 32 MB
__device__ __half g_acch  [(size_t)BB*HH*HD*NN];    // 32 MB
__device__ __half g_preh  [(size_t)MTOT * DD];      // 32 MB
__device__ __half g_wkvT  [(size_t)(2*DD) * DD];    // 4 MB [n][k], k|v weights
__device__ __half g_wgateT[(size_t)DD * DD];        // 2 MB
__device__ __half g_woutT [(size_t)DD * DD];        // 2 MB
__device__ __half g_wqh   [(size_t)DD * DD];        // 2 MB Wqkv[:, :1024] packed half
__device__ __half g_wcombT[(size_t)DD * DD];        // 2 MB (Wq@Wgate)^T half
__device__ float  g_bcomb [DD];
__device__ float  g_zeros [DD];                     // zero-initialized, never written
__device__ float  g_gains [NSCALES*HH];
__device__ float  g_sw    [2];
__device__ float  g_coup  [HH*HH];

// ---------------- helpers ----------------
__device__ __forceinline__ void cpa16(uint32_t s, const void* g) {
    asm volatile("cp.async.cg.shared.global [%0], [%1], 16;\n" :: "r"(s), "l"(g));
}
__device__ __forceinline__ void mma16816(float* d, const uint32_t* a, const uint32_t* b) {
    asm volatile(
        "mma.sync.aligned.m16n8k16.row.col.f32.f16.f16.f32 "
        "{%0,%1,%2,%3}, {%4,%5,%6,%7}, {%8,%9}, {%0,%1,%2,%3};\n"
        : "+f"(d[0]), "+f"(d[1]), "+f"(d[2]), "+f"(d[3])
        : "r"(a[0]), "r"(a[1]), "r"(a[2]), "r"(a[3]), "r"(b[0]), "r"(b[1]));
}
__device__ __forceinline__ void ldsm_x4(uint32_t& r0, uint32_t& r1, uint32_t& r2, uint32_t& r3,
                                        uint32_t addr) {
    asm volatile("ldmatrix.sync.aligned.m8n8.x4.shared.b16 {%0,%1,%2,%3}, [%4];"
                 : "=r"(r0), "=r"(r1), "=r"(r2), "=r"(r3) : "r"(addr));
}

// ---------------- K0: tiny prep ----------------
__global__ void prep_kernel(const float* __restrict__ scale_gain,
                            const float* __restrict__ skip_w,
                            const float* __restrict__ coupling) {
    int t = threadIdx.x;
    if (t < HH) {
        float m = -1e30f;
        for (int j = 0; j < NSCALES; j++) m = fmaxf(m, scale_gain[j*HH + t]);
        float e[NSCALES]; float s = 0.f;
        for (int j = 0; j < NSCALES; j++) { e[j] = expf(scale_gain[j*HH + t] - m); s += e[j]; }
        for (int j = 0; j < NSCALES; j++) g_gains[j*HH + t] = e[j] / s;
        float m2 = -1e30f;
        for (int j = 0; j < HH; j++) m2 = fmaxf(m2, coupling[t*HH + j]);
        float e2[HH]; float s2 = 0.f;
        for (int j = 0; j < HH; j++) { e2[j] = expf(coupling[t*HH + j] - m2); s2 += e2[j]; }
        for (int j = 0; j < HH; j++) g_coup[t*HH + j] = e2[j] / s2;
    }
    if (t < 2) g_sw[t] = 1.f / (1.f + expf(-skip_w[t]));
}

// ---- bcomb[j] = sum_l bqkv[l]*Wgate[l][j] + bgate[j] ----
__global__ __launch_bounds__(256)
void bcomb_kernel(const float* __restrict__ bqkv, const float* __restrict__ Wgate,
                  const float* __restrict__ bgate) {
    int j = blockIdx.x * 256 + threadIdx.x;
    float s = bgate[j];
    for (int l = 0; l < DD; l++) s += bqkv[l] * Wgate[(size_t)l*DD + j];
    g_bcomb[j] = s;
}

// ---------------- weight transpose to half: Wt[n][k] = (half)W[k][n] --------
__global__ __launch_bounds__(256)
void wtrans_kernel(const float* __restrict__ W, __half* __restrict__ Wt,
                   int K, int Nw) {
    __shared__ float s[32][33];
    int n0 = blockIdx.x * 32, k0 = blockIdx.y * 32;
    int tx = threadIdx.x & 31, ty = threadIdx.x >> 5;
    #pragma unroll
    for (int i = 0; i < 32; i += 8)
        s[ty + i][tx] = W[(size_t)(k0 + ty + i) * Nw + n0 + tx];
    __syncthreads();
    #pragma unroll
    for (int i = 0; i < 32; i += 8)
        Wt[(size_t)(n0 + ty + i) * K + k0 + tx] = __float2half_rn(s[tx][ty + i]);
}

// ---- pack Wqkv[:, :1024] to half row-major [i][l] ----
__global__ __launch_bounds__(256)
void qw_kernel(const float* __restrict__ Wqkv) {
    size_t idx = (size_t)blockIdx.x * 256 + threadIdx.x;   // over 1024*256 float4s
    int i = (int)(idx >> 8);
    int c = (int)(idx & 255);
    float4 v = *reinterpret_cast<const float4*>(Wqkv + (size_t)i*N3D + c*4);
    __half2 h01 = __floats2half2_rn(v.x, v.y);
    __half2 h23 = __floats2half2_rn(v.z, v.w);
    uint2 u = make_uint2(*(uint32_t*)&h01, *(uint32_t*)&h23);
    reinterpret_cast<uint2*>(g_wqh + (size_t)i*DD)[c] = u;
}

// ---------------- x -> half ----------------
__global__ __launch_bounds__(256)
void tohalf_kernel(const float* __restrict__ in, __half* __restrict__ out) {
    size_t i = (size_t)blockIdx.x * 256 + threadIdx.x;
    float4 v = reinterpret_cast<const float4*>(in)[i];
    __half2 h01 = __floats2half2_rn(v.x, v.y);
    __half2 h23 = __floats2half2_rn(v.z, v.w);
    uint2 u = make_uint2(*(uint32_t*)&h01, *(uint32_t*)&h23);
    reinterpret_cast<uint2*>(out)[i] = u;
}

// ===== fp16 mma.sync GEMM with ldmatrix feeds: C = A[M,K] @ Bt[N,K]^T + bias
// BM=BN=128, BK=64, 256 threads, 8 warps (2x4), warp tile 64x32, 3-stage.
#define STG_B 32768
#define NSTAGE 3
#define GSMEM (NSTAGE*STG_B)   // 98304 bytes

// MODE 0: C fp32 (+sigmoid if ACT).
// MODE 1: kv split: col<1024 -> k sum-of-squares partials; col>=1024 -> g_vh half.
// MODE 2: sigmoid -> g_gateh half.
// MODE 3: half -> g_wcombT.
template<int ACT, int MODE>
__global__ __launch_bounds__(256)
void mma_gemm(const __half* __restrict__ A,
              const __half* __restrict__ Bt,
              const float* __restrict__ bias,
              float* __restrict__ C, int ldc, int K) {
    extern __shared__ char smem[];
    const int tid  = threadIdx.x;
    const int lane = tid & 31;
    const int warp = tid >> 5;
    const int row0 = blockIdx.y * 128;
    const int col0 = blockIdx.x * 128;
    const int wr0  = (warp >> 2) * 64;
    const int wc0  = (warp & 3) * 32;
    const int lq   = lane >> 2;
    const int lr   = lane & 3;

    uint32_t sbase;
    asm("{ .reg .u64 t; cvta.to.shared.u64 t, %1; cvt.u32.u64 %0, t; }"
        : "=r"(sbase) : "l"((const void*)smem));

    float acc[4][4][4];
    #pragma unroll
    for (int r = 0; r < 4; r++)
        #pragma unroll
        for (int c = 0; c < 4; c++)
            #pragma unroll
            for (int e = 0; e < 4; e++) acc[r][c][e] = 0.f;

    auto load_stage = [&](int s, int kt) {
        uint32_t abase = sbase + s * STG_B;
        uint32_t bbase = abase + 16384;
        #pragma unroll
        for (int i = 0; i < 4; i++) {
            int c = tid + i * 256;
            int r = c >> 3, cc = c & 7;
            cpa16(abase + r * 128 + (((cc ^ r) & 7) << 4),
                  A + (size_t)(row0 + r) * K + kt * 64 + cc * 8);
        }
        #pragma unroll
        for (int i = 0; i < 4; i++) {
            int c = tid + i * 256;
            int r = c >> 3, cc = c & 7;
            cpa16(bbase + r * 128 + (((cc ^ r) & 7) << 4),
                  Bt + (size_t)(col0 + r) * K + kt * 64 + cc * 8);
        }
        asm volatile("cp.async.commit_group;\n");
    };

    const int KT = K >> 6;              // BK = 64
    load_stage(0, 0);
    load_stage(1, 1);

    const int aRowL = lane & 15;
    const int aCkL  = lane >> 4;
    const int bRowL = (lane & 7) + ((lane >> 4) << 3);
    const int bCkL  = (lane >> 3) & 1;

    for (int kt = 0; kt < KT; kt++) {
        if (kt + 1 < KT) asm volatile("cp.async.wait_group 1;\n");
        else             asm volatile("cp.async.wait_group 0;\n");
        __syncthreads();
        if (kt + 2 < KT) load_stage((kt + 2) % NSTAGE, kt + 2);

        uint32_t sA = sbase + (kt % NSTAGE) * STG_B;
        uint32_t sB = sA + 16384;
        #pragma unroll
        for (int kk = 0; kk < 64; kk += 16) {
            const int ck = kk >> 3;
            uint32_t af[4][4], bf[4][2];
            const int cA = ck + aCkL;
            #pragma unroll
            for (int rt = 0; rt < 4; rt++) {
                int r = wr0 + rt * 16 + aRowL;
                ldsm_x4(af[rt][0], af[rt][1], af[rt][2], af[rt][3],
                        sA + r * 128 + (((cA ^ r) & 7) << 4));
            }
            const int cB = ck + bCkL;
            #pragma unroll
            for (int p = 0; p < 2; p++) {
                int r = wc0 + p * 16 + bRowL;
                uint32_t m0, m1, m2, m3;
                ldsm_x4(m0, m1, m2, m3, sB + r * 128 + (((cB ^ r) & 7) << 4));
                bf[2*p][0] = m0; bf[2*p][1] = m1;
                bf[2*p+1][0] = m2; bf[2*p+1][1] = m3;
            }
            #pragma unroll
            for (int r = 0; r < 4; r++)
                #pragma unroll
                for (int c = 0; c < 4; c++)
                    mma16816(acc[r][c], af[r], bf[c]);
        }
        __syncthreads();
    }

    // ---- epilogue ----
    if (MODE == 1 && col0 < DD) {
        // k columns: reduce sum of squares; k is never stored.
        const int head = (col0 + wc0) >> 6;           // uniform per warp
        const int part = (wc0 >> 5) & 1;              // which 32-col half of the head
        #pragma unroll
        for (int r = 0; r < 4; r++) {
            int row = row0 + wr0 + r*16 + lq;
            float s0 = 0.f, s1 = 0.f;
            #pragma unroll
            for (int c = 0; c < 4; c++) {
                int col = col0 + wc0 + c*8 + lr*2;
                float2 b2 = *reinterpret_cast<const float2*>(bias + col);
                float v0 = acc[r][c][0] + b2.x, v1 = acc[r][c][1] + b2.y;
                float v2 = acc[r][c][2] + b2.x, v3 = acc[r][c][3] + b2.y;
                s0 += v0*v0 + v1*v1;
                s1 += v2*v2 + v3*v3;
            }
            s0 += __shfl_xor_sync(0xffffffffu, s0, 1);
            s0 += __shfl_xor_sync(0xffffffffu, s0, 2);
            s1 += __shfl_xor_sync(0xffffffffu, s1, 1);
            s1 += __shfl_xor_sync(0xffffffffu, s1, 2);
            if (lr == 0) {
                g_ksq2[((size_t)row*HH + head)*2 + part]     = s0;
                g_ksq2[((size_t)(row+8)*HH + head)*2 + part] = s1;
            }
        }
    } else {
        #pragma unroll
        for (int r = 0; r < 4; r++) {
            int row = row0 + wr0 + r*16 + lq;
            #pragma unroll
            for (int c = 0; c < 4; c++) {
                int col = col0 + wc0 + c*8 + lr*2;
                float2 b2 = *reinterpret_cast<const float2*>(bias + col);
                float v0 = acc[r][c][0] + b2.x, v1 = acc[r][c][1] + b2.y;
                float v2 = acc[r][c][2] + b2.x, v3 = acc[r][c][3] + b2.y;
                if (ACT) {
                    v0 = 1.f/(1.f + __expf(-v0)); v1 = 1.f/(1.f + __expf(-v1));
                    v2 = 1.f/(1.f + __expf(-v2)); v3 = 1.f/(1.f + __expf(-v3));
                }
                if (MODE == 0) {
                    *reinterpret_cast<float2*>(C + (size_t)row*ldc + col)     = make_float2(v0, v1);
                    *reinterpret_cast<float2*>(C + (size_t)(row+8)*ldc + col) = make_float2(v2, v3);
                } else {
                    __half2 h0 = __floats2half2_rn(v0, v1);
                    __half2 h1 = __floats2half2_rn(v2, v3);
                    if (MODE == 2) {
                        *(uint32_t*)(g_gateh + (size_t)row*DD + col)     = *(uint32_t*)&h0;
                        *(uint32_t*)(g_gateh + (size_t)(row+8)*DD + col) = *(uint32_t*)&h1;
                    } else if (MODE == 3) {
                        *(uint32_t*)(g_wcombT + (size_t)row*DD + col)     = *(uint32_t*)&h0;
                        *(uint32_t*)(g_wcombT + (size_t)(row+8)*DD + col) = *(uint32_t*)&h1;
                    } else {                  // MODE 1, v columns
                        int cc = col - DD;
                        *(uint32_t*)(g_vh + (size_t)row*DD + cc)     = *(uint32_t*)&h0;
                        *(uint32_t*)(g_vh + (size_t)(row+8)*DD + cc) = *(uint32_t*)&h1;
                    }
                }
            }
        }
    }
}

// ---------------- field[bh][d][n] = v * ||k|| -------------------------------
__global__ __launch_bounds__(256)
void field_kernel() {
    const int bh = blockIdx.y;
    const int b  = bh >> 4, h = bh & 15;
    const int n0 = blockIdx.x * 32;
    __shared__ float s_kmag[32];
    __shared__ float s_t[64][33];
    const int tid = threadIdx.x;
    if (tid < 32) {
        const float* kp = g_ksq2 + ((size_t)(b*NN + n0 + tid)*HH + h)*2;
        s_kmag[tid] = sqrtf(kp[0] + kp[1]);
    }
    __syncthreads();
    for (int idx = tid; idx < 2048; idx += 256) {
        int nl = idx >> 6, d = idx & 63;
        float v = __half2float(g_vh[(size_t)(b*NN + n0 + nl)*DD + h*HD + d]);
        s_t[d][nl] = v * s_kmag[nl];
    }
    __syncthreads();
    for (int idx = tid; idx < 2048; idx += 256) {
        int d = idx >> 5, nl = idx & 31;
        g_fieldh[((size_t)bh*HD + d)*NN + n0 + nl] = __float2half_rn(s_t[d][nl]);
    }
}

// ---------------- pyramid + sparse skips ------------------------------------
__global__ __launch_bounds__(256)
void pyramid_kernel() {
    const int r = blockIdx.x;               // bh*64 + d
    const int h = (r >> 6) & 15;
    const __half* row_g = g_fieldh + (size_t)r * NN;
    __shared__ float s_row[NN];
    __shared__ float s_acc[NN];
    const int tid = threadIdx.x;
    for (int i = tid; i < NN/8; i += 256) {
        uint4 u = reinterpret_cast<const uint4*>(row_g)[i];
        const __half2* hp = reinterpret_cast<const __half2*>(&u);
        float* dst = s_row + i*8;
        #pragma unroll
        for (int e = 0; e < 4; e++) {
            float2 f = __half22float2(hp[e]);
            dst[e*2] = f.x; dst[e*2+1] = f.y;
        }
    }
    float g[NSCALES];
    #pragma unroll
    for (int j = 0; j < NSCALES; j++) g[j] = g_gains[j*HH + h];
    const float sw0 = g_sw[0], sw1 = g_sw[1];
    __syncthreads();
    for (int n = tid; n < NN; n += 256) {
        float acc = 0.f;
        #pragma unroll
        for (int j = 0; j < NSCALES; j++) {
            int d = 1 << j;
            float y = C3 * s_row[n];
            if (n >= d)     y += C2 * s_row[n - d];
            if (n >= 2*d)   y += C1 * s_row[n - 2*d];
            if (n >= 3*d)   y += C0 * s_row[n - 3*d];
            acc += g[j] * y;
        }
        s_acc[n] = acc;
    }
    __syncthreads();
    __half* out_g = g_acch + (size_t)r * NN;
    for (int i = tid; i < NN/8; i += 256) {
        uint4 u;
        __half2* hp = reinterpret_cast<__half2*>(&u);
        #pragma unroll
        for (int e = 0; e < 4; e++) {
            int n = i*8 + e*2;
            float v0 = s_acc[n];
            float v1 = s_acc[n+1];
            if (n   >= 512)  v0 += sw0 * s_acc[n - 512];
            if (n+1 >= 512)  v1 += sw0 * s_acc[n+1 - 512];
            if (n   >= 1024) v0 += sw1 * s_acc[n - 1024];
            if (n+1 >= 1024) v1 += sw1 * s_acc[n+1 - 1024];
            hp[e] = __floats2half2_rn(v0, v1);
        }
        reinterpret_cast<uint4*>(out_g)[i] = u;
    }
}

// ------- fused coupling + transpose-back + gate + half-convert --------------
#define CGP 1040
#define CGSMEM (HH*CGP*4)   // 66560 bytes
__global__ __launch_bounds__(256)
void cg_kernel() {
    extern __shared__ float s[];
    __shared__ float sc[HH*HH];
    const int b  = blockIdx.y;
    const int n0 = blockIdx.x * 16;
    const int tid = threadIdx.x;
    if (tid < HH*HH) sc[tid] = g_coup[tid];
    for (int idx = tid; idx < 2048; idx += 256) {
        int row = idx >> 1, c8 = idx & 1;
        int j = row >> 6, d = row & 63;
        uint4 u = *reinterpret_cast<const uint4*>(
            g_acch + ((size_t)(b*HH + j)*HD + d)*NN + n0 + c8*8);
        const __half2* hp = reinterpret_cast<const __half2*>(&u);
        float* sp = s + j*CGP + d;
        #pragma unroll
        for (int e = 0; e < 4; e++) {
            float2 f = __half22float2(hp[e]);
            sp[(c8*8 + e*2)*64]     = f.x;
            sp[(c8*8 + e*2 + 1)*64] = f.y;
        }
    }
    __syncthreads();
    #pragma unroll
    for (int t = 0; t < 4; t++) {
        int p  = tid + 256*t;       // nl*64 + d
        int d  = p & 63, nl = p >> 6;
        float in[HH];
        #pragma unroll
        for (int j = 0; j < HH; j++) in[j] = s[j*CGP + nl*64 + d];
        #pragma unroll
        for (int h = 0; h < HH; h++) {
            float o = 0.f;
            #pragma unroll
            for (int j = 0; j < HH; j++) o += sc[h*HH + j] * in[j];
            size_t addr = ((size_t)(b*NN + n0 + nl))*DD + h*HD + d;
            float gt = __half2float(g_gateh[addr]);
            g_preh[addr] = __float2half_rn(o * gt);
        }
    }
}

// ---------------- launch ----------------------------------------------------
extern "C" void kernel_launch(void* const* d_in, const int* in_sizes, int n_in,
                              void* d_out, int out_size) {
    const float* x          = (const float*)d_in[0];
    const float* Wqkv       = (const float*)d_in[1];
    const float* bqkv       = (const float*)d_in[2];
    const float* Wout       = (const float*)d_in[3];
    const float* bout       = (const float*)d_in[4];
    const float* Wgate      = (const float*)d_in[5];
    const float* bgate      = (const float*)d_in[6];
    const float* scale_gain = (const float*)d_in[7];
    const float* skip_w     = (const float*)d_in[8];
    const float* coupling   = (const float*)d_in[9];
    float* out = (float*)d_out;

    __half *p_xh, *p_preh, *p_wkvT, *p_wgateT, *p_woutT, *p_wqh, *p_wcombT;
    float *p_bcomb, *p_zeros;
    cudaGetSymbolAddress((void**)&p_xh,     g_xh);
    cudaGetSymbolAddress((void**)&p_preh,   g_preh);
    cudaGetSymbolAddress((void**)&p_wkvT,   g_wkvT);
    cudaGetSymbolAddress((void**)&p_wgateT, g_wgateT);
    cudaGetSymbolAddress((void**)&p_woutT,  g_woutT);
    cudaGetSymbolAddress((void**)&p_wqh,    g_wqh);
    cudaGetSymbolAddress((void**)&p_wcombT, g_wcombT);
    cudaGetSymbolAddress((void**)&p_bcomb,  g_bcomb);
    cudaGetSymbolAddress((void**)&p_zeros,  g_zeros);

    cudaFuncSetAttribute(mma_gemm<0,1>, cudaFuncAttributeMaxDynamicSharedMemorySize, GSMEM);
    cudaFuncSetAttribute(mma_gemm<1,2>, cudaFuncAttributeMaxDynamicSharedMemorySize, GSMEM);
    cudaFuncSetAttribute(mma_gemm<0,0>, cudaFuncAttributeMaxDynamicSharedMemorySize, GSMEM);
    cudaFuncSetAttribute(mma_gemm<0,3>, cudaFuncAttributeMaxDynamicSharedMemorySize, GSMEM);
    cudaFuncSetAttribute(cg_kernel,     cudaFuncAttributeMaxDynamicSharedMemorySize, CGSMEM);

    prep_kernel<<<1, 32>>>(scale_gain, skip_w, coupling);
    bcomb_kernel<<<DD/256, 256>>>(bqkv, Wgate, bgate);

    // weights: kv-part of Wqkv transposed; Wgate/Wout transposed; Wq packed
    wtrans_kernel<<<dim3((2*DD)/32, DD/32), 256>>>(Wqkv + DD, p_wkvT, DD, N3D);
    wtrans_kernel<<<dim3(DD/32,  DD/32), 256>>>(Wgate, p_wgateT, DD, DD);
    wtrans_kernel<<<dim3(DD/32,  DD/32), 256>>>(Wout,  p_woutT,  DD, DD);
    qw_kernel<<<(DD*DD/4)/256, 256>>>(Wqkv);
    tohalf_kernel<<<(MTOT*DD/4)/256, 256>>>(x, p_xh);

    // WcombT[j][i] = sum_l WgateT[j][l] * Wq[i][l]   (half out)
    mma_gemm<0,3><<<dim3(DD/128, DD/128), 256, GSMEM>>>(
        p_wgateT, p_wqh, p_zeros, nullptr, 0, DD);
    // gate = sigmoid(x @ Wcomb + bcomb) -> half
    mma_gemm<1,2><<<dim3(DD/128, MTOT/128), 256, GSMEM>>>(
        p_xh, p_wcombT, p_bcomb, nullptr, 0, DD);
    // GEMM1: k|v = x @ Wkv + b  (k->sumsq partials, v->half)
    mma_gemm<0,1><<<dim3((2*DD)/128, MTOT/128), 256, GSMEM>>>(
        p_xh, p_wkvT, bqkv + DD, nullptr, 0, DD);

    field_kernel  <<<dim3(NN/32, BB*HH), 256>>>();
    pyramid_kernel<<<BB*HH*HD, 256>>>();
    cg_kernel     <<<dim3(NN/16, BB), 256, CGSMEM>>>();

    // GEMM3: out = pre @ Wout + bout
    mma_gemm<0,0><<<dim3(DD/128, MTOT/128), 256, GSMEM>>>(
        p_preh, p_woutT, bout, out, DD, DD);
}

// round 14
// speedup vs baseline: 1.1295x; 1.1295x over previous
#include <cuda_runtime.h>
#include <cuda_fp16.h>
#include <math.h>
#include <stdint.h>

// ---------------- problem constants ----------------
#define BB 4
#define NN 4096
#define DD 1024
#define HH 16
#define HD 64
#define MTOT (BB*NN)          // 16384
#define N3D (3*DD)            // 3072
#define NSCALES 11
#define NTAPS 24

#define C0 0.4829629131445341f
#define C1 0.8365163037378079f
#define C2 0.2241438680420134f
#define C3 (-0.1294095225512604f)

// ---------------- scratch (device globals; allocation-free) ----------------
__device__ __half g_xh    [(size_t)MTOT * DD];      // 32 MB
__device__ __half g_vh    [(size_t)MTOT * DD];      // 32 MB
__device__ float  g_ksq2  [(size_t)MTOT * HH * 2];  // 2 MB
__device__ __half g_gateh [(size_t)MTOT * DD];      // 32 MB
__device__ __half g_fieldh[(size_t)BB*HH*HD*NN];    // [bh][d][n] 32 MB
__device__ __half g_acch  [(size_t)BB*HH*HD*NN];    // 32 MB
__device__ __half g_preh  [(size_t)MTOT * DD];      // 32 MB
__device__ __half g_wkvT  [(size_t)(2*DD) * DD];    // 4 MB [n][k]
__device__ __half g_wgateT[(size_t)DD * DD];
__device__ __half g_woutT [(size_t)DD * DD];
__device__ __half g_wqh   [(size_t)DD * DD];        // Wqkv[:, :1024] packed half
__device__ __half g_wcombT[(size_t)DD * DD];        // (Wq@Wgate)^T half
__device__ float  g_bcombP[32][DD];                 // bcomb partials
__device__ float  g_bcomb [DD];
__device__ float  g_zeros [DD];                     // zero-initialized, never written
__device__ float  g_gains [NSCALES*HH];
__device__ float  g_tapc  [NTAPS*HH];               // merged tap coefs per head
__device__ float  g_sw    [2];
__device__ float  g_coup  [HH*HH];

// ---------------- helpers ----------------
__device__ __forceinline__ void cpa16(uint32_t s, const void* g) {
    asm volatile("cp.async.cg.shared.global [%0], [%1], 16;\n" :: "r"(s), "l"(g));
}
__device__ __forceinline__ void mma16816(float* d, const uint32_t* a, const uint32_t* b) {
    asm volatile(
        "mma.sync.aligned.m16n8k16.row.col.f32.f16.f16.f32 "
        "{%0,%1,%2,%3}, {%4,%5,%6,%7}, {%8,%9}, {%0,%1,%2,%3};\n"
        : "+f"(d[0]), "+f"(d[1]), "+f"(d[2]), "+f"(d[3])
        : "r"(a[0]), "r"(a[1]), "r"(a[2]), "r"(a[3]), "r"(b[0]), "r"(b[1]));
}
__device__ __forceinline__ void ldsm_x4(uint32_t& r0, uint32_t& r1, uint32_t& r2, uint32_t& r3,
                                        uint32_t addr) {
    asm volatile("ldmatrix.sync.aligned.m8n8.x4.shared.b16 {%0,%1,%2,%3}, [%4];"
                 : "=r"(r0), "=r"(r1), "=r"(r2), "=r"(r3) : "r"(addr));
}

// ---------------- K0: tiny prep (+ merged tap coefficients) ----------------
__global__ void prep_kernel(const float* __restrict__ scale_gain,
                            const float* __restrict__ skip_w,
                            const float* __restrict__ coupling) {
    int t = threadIdx.x;
    if (t < HH) {
        float m = -1e30f;
        for (int j = 0; j < NSCALES; j++) m = fmaxf(m, scale_gain[j*HH + t]);
        float e[NSCALES]; float s = 0.f;
        for (int j = 0; j < NSCALES; j++) { e[j] = expf(scale_gain[j*HH + t] - m); s += e[j]; }
        float g[NSCALES];
        for (int j = 0; j < NSCALES; j++) { g[j] = e[j] / s; g_gains[j*HH + t] = g[j]; }
        // merged taps: offset 0 -> C3 (softmax sums to 1)
        g_tapc[0*HH + t] = C3;
        // offsets 2^j, j=0..11 -> C2*g[j] (j<=10) + C1*g[j-1] (j>=1)
        for (int j = 0; j <= 11; j++) {
            float c = 0.f;
            if (j <= 10) c += C2 * g[j];
            if (j >= 1)  c += C1 * g[j-1];
            g_tapc[(1+j)*HH + t] = c;
        }
        // offsets 3*2^j, j=0..10 -> C0*g[j]
        for (int j = 0; j <= 10; j++) g_tapc[(13+j)*HH + t] = C0 * g[j];

        float m2 = -1e30f;
        for (int j = 0; j < HH; j++) m2 = fmaxf(m2, coupling[t*HH + j]);
        float e2[HH]; float s2 = 0.f;
        for (int j = 0; j < HH; j++) { e2[j] = expf(coupling[t*HH + j] - m2); s2 += e2[j]; }
        for (int j = 0; j < HH; j++) g_coup[t*HH + j] = e2[j] / s2;
    }
    if (t < 2) g_sw[t] = 1.f / (1.f + expf(-skip_w[t]));
}

// ---- bcomb: two-stage parallel reduction (coalesced) ----
__global__ __launch_bounds__(256)
void bcomb1_kernel(const float* __restrict__ bqkv, const float* __restrict__ Wgate) {
    int j = blockIdx.x * 256 + threadIdx.x;
    int part = blockIdx.y;                 // 32 parts of 32 l's
    float s = 0.f;
    #pragma unroll 8
    for (int l = part*32; l < part*32 + 32; l++)
        s += bqkv[l] * Wgate[(size_t)l*DD + j];
    g_bcombP[part][j] = s;
}
__global__ __launch_bounds__(256)
void bcomb2_kernel(const float* __restrict__ bgate) {
    int j = blockIdx.x * 256 + threadIdx.x;
    float s = bgate[j];
    #pragma unroll
    for (int p = 0; p < 32; p++) s += g_bcombP[p][j];
    g_bcomb[j] = s;
}

// ---------------- weight transpose to half: Wt[n][k] = (half)W[k][n] --------
__global__ __launch_bounds__(256)
void wtrans_kernel(const float* __restrict__ W, __half* __restrict__ Wt,
                   int K, int Nw) {
    __shared__ float s[32][33];
    int n0 = blockIdx.x * 32, k0 = blockIdx.y * 32;
    int tx = threadIdx.x & 31, ty = threadIdx.x >> 5;
    #pragma unroll
    for (int i = 0; i < 32; i += 8)
        s[ty + i][tx] = W[(size_t)(k0 + ty + i) * Nw + n0 + tx];
    __syncthreads();
    #pragma unroll
    for (int i = 0; i < 32; i += 8)
        Wt[(size_t)(n0 + ty + i) * K + k0 + tx] = __float2half_rn(s[tx][ty + i]);
}

// ---- pack Wqkv[:, :1024] to half row-major [i][l] ----
__global__ __launch_bounds__(256)
void qw_kernel(const float* __restrict__ Wqkv) {
    size_t idx = (size_t)blockIdx.x * 256 + threadIdx.x;
    int i = (int)(idx >> 8);
    int c = (int)(idx & 255);
    float4 v = *reinterpret_cast<const float4*>(Wqkv + (size_t)i*N3D + c*4);
    __half2 h01 = __floats2half2_rn(v.x, v.y);
    __half2 h23 = __floats2half2_rn(v.z, v.w);
    uint2 u = make_uint2(*(uint32_t*)&h01, *(uint32_t*)&h23);
    reinterpret_cast<uint2*>(g_wqh + (size_t)i*DD)[c] = u;
}

// ---------------- x -> half ----------------
__global__ __launch_bounds__(256)
void tohalf_kernel(const float* __restrict__ in, __half* __restrict__ out) {
    size_t i = (size_t)blockIdx.x * 256 + threadIdx.x;
    float4 v = reinterpret_cast<const float4*>(in)[i];
    __half2 h01 = __floats2half2_rn(v.x, v.y);
    __half2 h23 = __floats2half2_rn(v.z, v.w);
    uint2 u = make_uint2(*(uint32_t*)&h01, *(uint32_t*)&h23);
    reinterpret_cast<uint2*>(out)[i] = u;
}

// ===== fp16 mma.sync GEMM with ldmatrix feeds: C = A[M,K] @ Bt[N,K]^T + bias
#define STG_B 32768
#define NSTAGE 3
#define GSMEM (NSTAGE*STG_B)   // 98304 bytes

// MODE 0: C fp32 (+sigmoid if ACT).
// MODE 1: kv split: col<1024 -> k sum-of-squares partials; col>=1024 -> g_vh half.
// MODE 2: sigmoid -> g_gateh half.  MODE 3: half -> g_wcombT.
template<int ACT, int MODE>
__global__ __launch_bounds__(256)
void mma_gemm(const __half* __restrict__ A,
              const __half* __restrict__ Bt,
              const float* __restrict__ bias,
              float* __restrict__ C, int ldc, int K) {
    extern __shared__ char smem[];
    const int tid  = threadIdx.x;
    const int lane = tid & 31;
    const int warp = tid >> 5;
    const int row0 = blockIdx.y * 128;
    const int col0 = blockIdx.x * 128;
    const int wr0  = (warp >> 2) * 64;
    const int wc0  = (warp & 3) * 32;
    const int lq   = lane >> 2;
    const int lr   = lane & 3;

    uint32_t sbase;
    asm("{ .reg .u64 t; cvta.to.shared.u64 t, %1; cvt.u32.u64 %0, t; }"
        : "=r"(sbase) : "l"((const void*)smem));

    float acc[4][4][4];
    #pragma unroll
    for (int r = 0; r < 4; r++)
        #pragma unroll
        for (int c = 0; c < 4; c++)
            #pragma unroll
            for (int e = 0; e < 4; e++) acc[r][c][e] = 0.f;

    auto load_stage = [&](int s, int kt) {
        uint32_t abase = sbase + s * STG_B;
        uint32_t bbase = abase + 16384;
        #pragma unroll
        for (int i = 0; i < 4; i++) {
            int c = tid + i * 256;
            int r = c >> 3, cc = c & 7;
            cpa16(abase + r * 128 + (((cc ^ r) & 7) << 4),
                  A + (size_t)(row0 + r) * K + kt * 64 + cc * 8);
        }
        #pragma unroll
        for (int i = 0; i < 4; i++) {
            int c = tid + i * 256;
            int r = c >> 3, cc = c & 7;
            cpa16(bbase + r * 128 + (((cc ^ r) & 7) << 4),
                  Bt + (size_t)(col0 + r) * K + kt * 64 + cc * 8);
        }
        asm volatile("cp.async.commit_group;\n");
    };

    const int KT = K >> 6;
    load_stage(0, 0);
    load_stage(1, 1);

    const int aRowL = lane & 15;
    const int aCkL  = lane >> 4;
    const int bRowL = (lane & 7) + ((lane >> 4) << 3);
    const int bCkL  = (lane >> 3) & 1;

    for (int kt = 0; kt < KT; kt++) {
        if (kt + 1 < KT) asm volatile("cp.async.wait_group 1;\n");
        else             asm volatile("cp.async.wait_group 0;\n");
        __syncthreads();
        if (kt + 2 < KT) load_stage((kt + 2) % NSTAGE, kt + 2);

        uint32_t sA = sbase + (kt % NSTAGE) * STG_B;
        uint32_t sB = sA + 16384;
        #pragma unroll
        for (int kk = 0; kk < 64; kk += 16) {
            const int ck = kk >> 3;
            uint32_t af[4][4], bf[4][2];
            const int cA = ck + aCkL;
            #pragma unroll
            for (int rt = 0; rt < 4; rt++) {
                int r = wr0 + rt * 16 + aRowL;
                ldsm_x4(af[rt][0], af[rt][1], af[rt][2], af[rt][3],
                        sA + r * 128 + (((cA ^ r) & 7) << 4));
            }
            const int cB = ck + bCkL;
            #pragma unroll
            for (int p = 0; p < 2; p++) {
                int r = wc0 + p * 16 + bRowL;
                uint32_t m0, m1, m2, m3;
                ldsm_x4(m0, m1, m2, m3, sB + r * 128 + (((cB ^ r) & 7) << 4));
                bf[2*p][0] = m0; bf[2*p][1] = m1;
                bf[2*p+1][0] = m2; bf[2*p+1][1] = m3;
            }
            #pragma unroll
            for (int r = 0; r < 4; r++)
                #pragma unroll
                for (int c = 0; c < 4; c++)
                    mma16816(acc[r][c], af[r], bf[c]);
        }
        __syncthreads();
    }

    // ---- epilogue ----
    if (MODE == 1 && col0 < DD) {
        const int head = (col0 + wc0) >> 6;
        const int part = (wc0 >> 5) & 1;
        #pragma unroll
        for (int r = 0; r < 4; r++) {
            int row = row0 + wr0 + r*16 + lq;
            float s0 = 0.f, s1 = 0.f;
            #pragma unroll
            for (int c = 0; c < 4; c++) {
                int col = col0 + wc0 + c*8 + lr*2;
                float2 b2 = *reinterpret_cast<const float2*>(bias + col);
                float v0 = acc[r][c][0] + b2.x, v1 = acc[r][c][1] + b2.y;
                float v2 = acc[r][c][2] + b2.x, v3 = acc[r][c][3] + b2.y;
                s0 += v0*v0 + v1*v1;
                s1 += v2*v2 + v3*v3;
            }
            s0 += __shfl_xor_sync(0xffffffffu, s0, 1);
            s0 += __shfl_xor_sync(0xffffffffu, s0, 2);
            s1 += __shfl_xor_sync(0xffffffffu, s1, 1);
            s1 += __shfl_xor_sync(0xffffffffu, s1, 2);
            if (lr == 0) {
                g_ksq2[((size_t)row*HH + head)*2 + part]     = s0;
                g_ksq2[((size_t)(row+8)*HH + head)*2 + part] = s1;
            }
        }
    } else {
        #pragma unroll
        for (int r = 0; r < 4; r++) {
            int row = row0 + wr0 + r*16 + lq;
            #pragma unroll
            for (int c = 0; c < 4; c++) {
                int col = col0 + wc0 + c*8 + lr*2;
                float2 b2 = *reinterpret_cast<const float2*>(bias + col);
                float v0 = acc[r][c][0] + b2.x, v1 = acc[r][c][1] + b2.y;
                float v2 = acc[r][c][2] + b2.x, v3 = acc[r][c][3] + b2.y;
                if (ACT) {
                    v0 = 1.f/(1.f + __expf(-v0)); v1 = 1.f/(1.f + __expf(-v1));
                    v2 = 1.f/(1.f + __expf(-v2)); v3 = 1.f/(1.f + __expf(-v3));
                }
                if (MODE == 0) {
                    *reinterpret_cast<float2*>(C + (size_t)row*ldc + col)     = make_float2(v0, v1);
                    *reinterpret_cast<float2*>(C + (size_t)(row+8)*ldc + col) = make_float2(v2, v3);
                } else {
                    __half2 h0 = __floats2half2_rn(v0, v1);
                    __half2 h1 = __floats2half2_rn(v2, v3);
                    if (MODE == 2) {
                        *(uint32_t*)(g_gateh + (size_t)row*DD + col)     = *(uint32_t*)&h0;
                        *(uint32_t*)(g_gateh + (size_t)(row+8)*DD + col) = *(uint32_t*)&h1;
                    } else if (MODE == 3) {
                        *(uint32_t*)(g_wcombT + (size_t)row*DD + col)     = *(uint32_t*)&h0;
                        *(uint32_t*)(g_wcombT + (size_t)(row+8)*DD + col) = *(uint32_t*)&h1;
                    } else {
                        int cc = col - DD;
                        *(uint32_t*)(g_vh + (size_t)row*DD + cc)     = *(uint32_t*)&h0;
                        *(uint32_t*)(g_vh + (size_t)(row+8)*DD + cc) = *(uint32_t*)&h1;
                    }
                }
            }
        }
    }
}

// ---------------- field[bh][d][n] = v * ||k|| -------------------------------
__global__ __launch_bounds__(256)
void field_kernel() {
    const int bh = blockIdx.y;
    const int b  = bh >> 4, h = bh & 15;
    const int n0 = blockIdx.x * 32;
    __shared__ float s_kmag[32];
    __shared__ float s_t[64][33];
    const int tid = threadIdx.x;
    if (tid < 32) {
        const float* kp = g_ksq2 + ((size_t)(b*NN + n0 + tid)*HH + h)*2;
        s_kmag[tid] = sqrtf(kp[0] + kp[1]);
    }
    __syncthreads();
    for (int idx = tid; idx < 2048; idx += 256) {
        int nl = idx >> 6, d = idx & 63;
        float v = __half2float(g_vh[(size_t)(b*NN + n0 + nl)*DD + h*HD + d]);
        s_t[d][nl] = v * s_kmag[nl];
    }
    __syncthreads();
    for (int idx = tid; idx < 2048; idx += 256) {
        int d = idx >> 5, nl = idx & 31;
        g_fieldh[((size_t)bh*HD + d)*NN + n0 + nl] = __float2half_rn(s_t[d][nl]);
    }
}

// ---------- pyramid: 24 merged taps, zero-padded, half2 pairs ---------------
#define PADH 3072
#define PADA 1024
__global__ __launch_bounds__(256)
void pyramid_kernel() {
    const int r = blockIdx.x;               // bh*64 + d
    const int h = (r >> 6) & 15;
    const __half* row_g = g_fieldh + (size_t)r * NN;
    __shared__ __align__(16) __half s_row[PADH + NN];   // 14336 B
    __shared__ __align__(16) float  s_acc[PADA + NN];   // 20480 B
    const int tid = threadIdx.x;

    // zero pads
    for (int i = tid; i < PADH/8; i += 256)
        reinterpret_cast<uint4*>(s_row)[i] = make_uint4(0,0,0,0);
    for (int i = tid; i < PADA/4; i += 256)
        reinterpret_cast<float4*>(s_acc)[i] = make_float4(0.f,0.f,0.f,0.f);
    // load row
    for (int i = tid; i < NN/8; i += 256)
        reinterpret_cast<uint4*>(s_row + PADH)[i] =
            reinterpret_cast<const uint4*>(row_g)[i];

    // merged tap coefs for this head
    float c[NTAPS];
    #pragma unroll
    for (int t = 0; t < NTAPS; t++) c[t] = g_tapc[t*HH + h];
    const float sw0 = g_sw[0], sw1 = g_sw[1];
    __syncthreads();

    const __half2* rowp = reinterpret_cast<const __half2*>(s_row);
    // generic taps: index into c[], half2 offset = OFF/2 (all OFF even here)
    constexpr int GT = 19;
    constexpr int gidx[GT] = {4,5,6,7,8,9,10,11,12,  14,15,16,17,18,19,20,21,22,23};
    constexpr int goff[GT] = {4,8,16,32,64,128,256,512,1024,  3,6,12,24,48,96,192,384,768,1536};
    // goff stores OFF/2: for c[1+j] OFF=2^j (j=3..11 -> OFF/2 = 4..1024);
    // for c[13+j] OFF=3*2^j (j=1..10 -> OFF/2 = 3,6,...,1536)

    for (int ip = tid; ip < NN/2; ip += 256) {
        const int base = PADH/2 + ip;       // h2 idx of pair (n, n+1), n = 2*ip
        float2 f0 = __half22float2(rowp[base]);     // x[n],   x[n+1]
        float2 f1 = __half22float2(rowp[base-1]);   // x[n-2], x[n-1]
        float2 f2 = __half22float2(rowp[base-2]);   // x[n-4], x[n-3]
        // taps 0 (off0), 1 (off1), 2 (off2), 13 (off3), 3 (off4)
        float a0 = c[0]*f0.x + c[1]*f1.y + c[2]*f1.x + c[13]*f2.y + c[3]*f2.x;
        float a1 = c[0]*f0.y + c[1]*f0.x + c[2]*f1.y + c[13]*f1.x + c[3]*f2.y;
        #pragma unroll
        for (int t = 0; t < GT; t++) {
            float2 f = __half22float2(rowp[base - goff[t]]);
            a0 += c[gidx[t]]*f.x;
            a1 += c[gidx[t]]*f.y;
        }
        s_acc[PADA + 2*ip]     = a0;
        s_acc[PADA + 2*ip + 1] = a1;
    }
    __syncthreads();

    __half* out_g = g_acch + (size_t)r * NN;
    for (int ip = tid; ip < NN/2; ip += 256) {
        int n = 2*ip;
        float2 v  = *reinterpret_cast<float2*>(&s_acc[PADA + n]);
        float2 a  = *reinterpret_cast<float2*>(&s_acc[PADA + n - 512]);
        float2 b  = *reinterpret_cast<float2*>(&s_acc[PADA + n - 1024]);
        v.x += sw0*a.x + sw1*b.x;
        v.y += sw0*a.y + sw1*b.y;
        __half2 hv = __floats2half2_rn(v.x, v.y);
        *reinterpret_cast<uint32_t*>(out_g + n) = *reinterpret_cast<uint32_t*>(&hv);
    }
}

// ------- fused coupling + transpose-back + gate + half-convert --------------
#define CGP 1040
#define CGSMEM (HH*CGP*4)   // 66560 bytes
__global__ __launch_bounds__(256)
void cg_kernel() {
    extern __shared__ float s[];
    __shared__ float sc[HH*HH];
    const int b  = blockIdx.y;
    const int n0 = blockIdx.x * 16;
    const int tid = threadIdx.x;
    if (tid < HH*HH) sc[tid] = g_coup[tid];
    for (int idx = tid; idx < 2048; idx += 256) {
        int row = idx >> 1, c8 = idx & 1;
        int j = row >> 6, d = row & 63;
        uint4 u = *reinterpret_cast<const uint4*>(
            g_acch + ((size_t)(b*HH + j)*HD + d)*NN + n0 + c8*8);
        const __half2* hp = reinterpret_cast<const __half2*>(&u);
        float* sp = s + j*CGP + d;
        #pragma unroll
        for (int e = 0; e < 4; e++) {
            float2 f = __half22float2(hp[e]);
            sp[(c8*8 + e*2)*64]     = f.x;
            sp[(c8*8 + e*2 + 1)*64] = f.y;
        }
    }
    __syncthreads();
    #pragma unroll
    for (int t = 0; t < 4; t++) {
        int p  = tid + 256*t;       // nl*64 + d
        int d  = p & 63, nl = p >> 6;
        float in[HH];
        #pragma unroll
        for (int j = 0; j < HH; j++) in[j] = s[j*CGP + nl*64 + d];
        #pragma unroll
        for (int h = 0; h < HH; h++) {
            float o = 0.f;
            #pragma unroll
            for (int j = 0; j < HH; j++) o += sc[h*HH + j] * in[j];
            size_t addr = ((size_t)(b*NN + n0 + nl))*DD + h*HD + d;
            float gt = __half2float(g_gateh[addr]);
            g_preh[addr] = __float2half_rn(o * gt);
        }
    }
}

// ---------------- launch ----------------------------------------------------
extern "C" void kernel_launch(void* const* d_in, const int* in_sizes, int n_in,
                              void* d_out, int out_size) {
    const float* x          = (const float*)d_in[0];
    const float* Wqkv       = (const float*)d_in[1];
    const float* bqkv       = (const float*)d_in[2];
    const float* Wout       = (const float*)d_in[3];
    const float* bout       = (const float*)d_in[4];
    const float* Wgate      = (const float*)d_in[5];
    const float* bgate      = (const float*)d_in[6];
    const float* scale_gain = (const float*)d_in[7];
    const float* skip_w     = (const float*)d_in[8];
    const float* coupling   = (const float*)d_in[9];
    float* out = (float*)d_out;

    __half *p_xh, *p_preh, *p_wkvT, *p_wgateT, *p_woutT, *p_wqh, *p_wcombT;
    float *p_bcomb, *p_zeros;
    cudaGetSymbolAddress((void**)&p_xh,     g_xh);
    cudaGetSymbolAddress((void**)&p_preh,   g_preh);
    cudaGetSymbolAddress((void**)&p_wkvT,   g_wkvT);
    cudaGetSymbolAddress((void**)&p_wgateT, g_wgateT);
    cudaGetSymbolAddress((void**)&p_woutT,  g_woutT);
    cudaGetSymbolAddress((void**)&p_wqh,    g_wqh);
    cudaGetSymbolAddress((void**)&p_wcombT, g_wcombT);
    cudaGetSymbolAddress((void**)&p_bcomb,  g_bcomb);
    cudaGetSymbolAddress((void**)&p_zeros,  g_zeros);

    cudaFuncSetAttribute(mma_gemm<0,1>, cudaFuncAttributeMaxDynamicSharedMemorySize, GSMEM);
    cudaFuncSetAttribute(mma_gemm<1,2>, cudaFuncAttributeMaxDynamicSharedMemorySize, GSMEM);
    cudaFuncSetAttribute(mma_gemm<0,0>, cudaFuncAttributeMaxDynamicSharedMemorySize, GSMEM);
    cudaFuncSetAttribute(mma_gemm<0,3>, cudaFuncAttributeMaxDynamicSharedMemorySize, GSMEM);
    cudaFuncSetAttribute(cg_kernel,     cudaFuncAttributeMaxDynamicSharedMemorySize, CGSMEM);

    prep_kernel<<<1, 32>>>(scale_gain, skip_w, coupling);
    bcomb1_kernel<<<dim3(DD/256, 32), 256>>>(bqkv, Wgate);
    bcomb2_kernel<<<DD/256, 256>>>(bgate);

    wtrans_kernel<<<dim3((2*DD)/32, DD/32), 256>>>(Wqkv + DD, p_wkvT, DD, N3D);
    wtrans_kernel<<<dim3(DD/32,  DD/32), 256>>>(Wgate, p_wgateT, DD, DD);
    wtrans_kernel<<<dim3(DD/32,  DD/32), 256>>>(Wout,  p_woutT,  DD, DD);
    qw_kernel<<<(DD*DD/4)/256, 256>>>(Wqkv);
    tohalf_kernel<<<(MTOT*DD/4)/256, 256>>>(x, p_xh);

    // WcombT = WgateT @ Wq^T (half out)
    mma_gemm<0,3><<<dim3(DD/128, DD/128), 256, GSMEM>>>(
        p_wgateT, p_wqh, p_zeros, nullptr, 0, DD);
    // gate = sigmoid(x @ Wcomb + bcomb) -> half
    mma_gemm<1,2><<<dim3(DD/128, MTOT/128), 256, GSMEM>>>(
        p_xh, p_wcombT, p_bcomb, nullptr, 0, DD);
    // k|v = x @ Wkv + b  (k->sumsq partials, v->half)
    mma_gemm<0,1><<<dim3((2*DD)/128, MTOT/128), 256, GSMEM>>>(
        p_xh, p_wkvT, bqkv + DD, nullptr, 0, DD);

    field_kernel  <<<dim3(NN/32, BB*HH), 256>>>();
    pyramid_kernel<<<BB*HH*HD, 256>>>();
    cg_kernel     <<<dim3(NN/16, BB), 256, CGSMEM>>>();

    // out = pre @ Wout + bout
    mma_gemm<0,0><<<dim3(DD/128, MTOT/128), 256, GSMEM>>>(
        p_preh, p_woutT, bout, out, DD, DD);
}

// round 15
// speedup vs baseline: 1.1337x; 1.0037x over previous
#include <cuda_runtime.h>
#include <cuda_fp16.h>
#include <math.h>
#include <stdint.h>

// ---------------- problem constants ----------------
#define BB 4
#define NN 4096
#define DD 1024
#define HH 16
#define HD 64
#define MTOT (BB*NN)          // 16384
#define N3D (3*DD)            // 3072
#define NSCALES 11
#define NTAPS 24

#define C0 0.4829629131445341f
#define C1 0.8365163037378079f
#define C2 0.2241438680420134f
#define C3 (-0.1294095225512604f)

// ---------------- scratch (device globals; allocation-free) ----------------
__device__ __half g_xh    [(size_t)MTOT * DD];      // 32 MB
__device__ __half g_vh    [(size_t)MTOT * DD];      // 32 MB
__device__ float  g_ksq2  [(size_t)MTOT * HH * 2];  // 2 MB
__device__ __half g_gateh [(size_t)MTOT * DD];      // 32 MB
__device__ __half g_fieldh[(size_t)BB*HH*HD*NN];    // [bh][d][n] 32 MB
__device__ __half g_acch  [(size_t)BB*HH*HD*NN];    // 32 MB
__device__ __half g_preh  [(size_t)MTOT * DD];      // 32 MB
__device__ __half g_wallT [(size_t)N3D * DD];       // 6 MB: rows 0-1023 wcombT, 1024-3071 wkvT
__device__ __half g_wgateT[(size_t)DD * DD];
__device__ __half g_woutT [(size_t)DD * DD];
__device__ __half g_wqh   [(size_t)DD * DD];        // Wqkv[:, :1024] packed half
__device__ float  g_bcombP[32][DD];                 // bcomb partials
__device__ float  g_bias3 [N3D];                    // bcomb | bqkv[1024:3072]
__device__ float  g_zeros [DD];                     // zero-initialized, never written
__device__ float  g_gains [NSCALES*HH];
__device__ float  g_tapc  [NTAPS*HH];               // merged tap coefs per head
__device__ float  g_sw    [2];
__device__ float  g_coup  [HH*HH];

// ---------------- helpers ----------------
__device__ __forceinline__ void cpa16(uint32_t s, const void* g) {
    asm volatile("cp.async.cg.shared.global [%0], [%1], 16;\n" :: "r"(s), "l"(g));
}
__device__ __forceinline__ void mma16816(float* d, const uint32_t* a, const uint32_t* b) {
    asm volatile(
        "mma.sync.aligned.m16n8k16.row.col.f32.f16.f16.f32 "
        "{%0,%1,%2,%3}, {%4,%5,%6,%7}, {%8,%9}, {%0,%1,%2,%3};\n"
        : "+f"(d[0]), "+f"(d[1]), "+f"(d[2]), "+f"(d[3])
        : "r"(a[0]), "r"(a[1]), "r"(a[2]), "r"(a[3]), "r"(b[0]), "r"(b[1]));
}
__device__ __forceinline__ void ldsm_x4(uint32_t& r0, uint32_t& r1, uint32_t& r2, uint32_t& r3,
                                        uint32_t addr) {
    asm volatile("ldmatrix.sync.aligned.m8n8.x4.shared.b16 {%0,%1,%2,%3}, [%4];"
                 : "=r"(r0), "=r"(r1), "=r"(r2), "=r"(r3) : "r"(addr));
}

// ---------------- K0: tiny prep (+ merged tap coefficients) ----------------
__global__ void prep_kernel(const float* __restrict__ scale_gain,
                            const float* __restrict__ skip_w,
                            const float* __restrict__ coupling) {
    int t = threadIdx.x;
    if (t < HH) {
        float m = -1e30f;
        for (int j = 0; j < NSCALES; j++) m = fmaxf(m, scale_gain[j*HH + t]);
        float e[NSCALES]; float s = 0.f;
        for (int j = 0; j < NSCALES; j++) { e[j] = expf(scale_gain[j*HH + t] - m); s += e[j]; }
        float g[NSCALES];
        for (int j = 0; j < NSCALES; j++) { g[j] = e[j] / s; g_gains[j*HH + t] = g[j]; }
        g_tapc[0*HH + t] = C3;
        for (int j = 0; j <= 11; j++) {
            float c = 0.f;
            if (j <= 10) c += C2 * g[j];
            if (j >= 1)  c += C1 * g[j-1];
            g_tapc[(1+j)*HH + t] = c;
        }
        for (int j = 0; j <= 10; j++) g_tapc[(13+j)*HH + t] = C0 * g[j];

        float m2 = -1e30f;
        for (int j = 0; j < HH; j++) m2 = fmaxf(m2, coupling[t*HH + j]);
        float e2[HH]; float s2 = 0.f;
        for (int j = 0; j < HH; j++) { e2[j] = expf(coupling[t*HH + j] - m2); s2 += e2[j]; }
        for (int j = 0; j < HH; j++) g_coup[t*HH + j] = e2[j] / s2;
    }
    if (t < 2) g_sw[t] = 1.f / (1.f + expf(-skip_w[t]));
}

// ---- bcomb stage 1: coalesced partials ----
__global__ __launch_bounds__(256)
void bcomb1_kernel(const float* __restrict__ bqkv, const float* __restrict__ Wgate) {
    int j = blockIdx.x * 256 + threadIdx.x;
    int part = blockIdx.y;
    float s = 0.f;
    #pragma unroll 8
    for (int l = part*32; l < part*32 + 32; l++)
        s += bqkv[l] * Wgate[(size_t)l*DD + j];
    g_bcombP[part][j] = s;
}
// ---- bias3: j<DD -> bcomb; else copy bqkv[j] ----
__global__ __launch_bounds__(256)
void bias3_kernel(const float* __restrict__ bgate, const float* __restrict__ bqkv) {
    int j = blockIdx.x * 256 + threadIdx.x;
    if (j < DD) {
        float s = bgate[j];
        #pragma unroll
        for (int p = 0; p < 32; p++) s += g_bcombP[p][j];
        g_bias3[j] = s;
    } else {
        g_bias3[j] = bqkv[j];
    }
}

// ---------------- weight transpose to half: Wt[n][k] = (half)W[k][n] --------
__global__ __launch_bounds__(256)
void wtrans_kernel(const float* __restrict__ W, __half* __restrict__ Wt,
                   int K, int Nw) {
    __shared__ float s[32][33];
    int n0 = blockIdx.x * 32, k0 = blockIdx.y * 32;
    int tx = threadIdx.x & 31, ty = threadIdx.x >> 5;
    #pragma unroll
    for (int i = 0; i < 32; i += 8)
        s[ty + i][tx] = W[(size_t)(k0 + ty + i) * Nw + n0 + tx];
    __syncthreads();
    #pragma unroll
    for (int i = 0; i < 32; i += 8)
        Wt[(size_t)(n0 + ty + i) * K + k0 + tx] = __float2half_rn(s[tx][ty + i]);
}

// ---- pack Wqkv[:, :1024] to half row-major [i][l] ----
__global__ __launch_bounds__(256)
void qw_kernel(const float* __restrict__ Wqkv) {
    size_t idx = (size_t)blockIdx.x * 256 + threadIdx.x;
    int i = (int)(idx >> 8);
    int c = (int)(idx & 255);
    float4 v = *reinterpret_cast<const float4*>(Wqkv + (size_t)i*N3D + c*4);
    __half2 h01 = __floats2half2_rn(v.x, v.y);
    __half2 h23 = __floats2half2_rn(v.z, v.w);
    uint2 u = make_uint2(*(uint32_t*)&h01, *(uint32_t*)&h23);
    reinterpret_cast<uint2*>(g_wqh + (size_t)i*DD)[c] = u;
}

// ---------------- x -> half ----------------
__global__ __launch_bounds__(256)
void tohalf_kernel(const float* __restrict__ in, __half* __restrict__ out) {
    size_t i = (size_t)blockIdx.x * 256 + threadIdx.x;
    float4 v = reinterpret_cast<const float4*>(in)[i];
    __half2 h01 = __floats2half2_rn(v.x, v.y);
    __half2 h23 = __floats2half2_rn(v.z, v.w);
    uint2 u = make_uint2(*(uint32_t*)&h01, *(uint32_t*)&h23);
    reinterpret_cast<uint2*>(out)[i] = u;
}

// ===== fp16 mma.sync GEMM with ldmatrix feeds: C = A[M,K] @ Bt[N,K]^T + bias
#define STG_B 32768
#define NSTAGE 3
#define GSMEM (NSTAGE*STG_B)   // 98304 bytes

// MODE 0: C fp32 (+sigmoid if ACT).
// MODE 3: half -> g_wallT (wcomb region, rows 0..1023).
// MODE 4: merged epilogue: col0<1024 -> sigmoid -> g_gateh;
//         1024..2047 -> k sum-of-squares partials; >=2048 -> g_vh half.
template<int ACT, int MODE>
__global__ __launch_bounds__(256)
void mma_gemm(const __half* __restrict__ A,
              const __half* __restrict__ Bt,
              const float* __restrict__ bias,
              float* __restrict__ C, int ldc, int K) {
    extern __shared__ char smem[];
    const int tid  = threadIdx.x;
    const int lane = tid & 31;
    const int warp = tid >> 5;
    const int row0 = blockIdx.y * 128;
    const int col0 = blockIdx.x * 128;
    const int wr0  = (warp >> 2) * 64;
    const int wc0  = (warp & 3) * 32;
    const int lq   = lane >> 2;
    const int lr   = lane & 3;

    uint32_t sbase;
    asm("{ .reg .u64 t; cvta.to.shared.u64 t, %1; cvt.u32.u64 %0, t; }"
        : "=r"(sbase) : "l"((const void*)smem));

    float acc[4][4][4];
    #pragma unroll
    for (int r = 0; r < 4; r++)
        #pragma unroll
        for (int c = 0; c < 4; c++)
            #pragma unroll
            for (int e = 0; e < 4; e++) acc[r][c][e] = 0.f;

    auto load_stage = [&](int s, int kt) {
        uint32_t abase = sbase + s * STG_B;
        uint32_t bbase = abase + 16384;
        #pragma unroll
        for (int i = 0; i < 4; i++) {
            int c = tid + i * 256;
            int r = c >> 3, cc = c & 7;
            cpa16(abase + r * 128 + (((cc ^ r) & 7) << 4),
                  A + (size_t)(row0 + r) * K + kt * 64 + cc * 8);
        }
        #pragma unroll
        for (int i = 0; i < 4; i++) {
            int c = tid + i * 256;
            int r = c >> 3, cc = c & 7;
            cpa16(bbase + r * 128 + (((cc ^ r) & 7) << 4),
                  Bt + (size_t)(col0 + r) * K + kt * 64 + cc * 8);
        }
        asm volatile("cp.async.commit_group;\n");
    };

    const int KT = K >> 6;
    load_stage(0, 0);
    load_stage(1, 1);

    const int aRowL = lane & 15;
    const int aCkL  = lane >> 4;
    const int bRowL = (lane & 7) + ((lane >> 4) << 3);
    const int bCkL  = (lane >> 3) & 1;

    for (int kt = 0; kt < KT; kt++) {
        if (kt + 1 < KT) asm volatile("cp.async.wait_group 1;\n");
        else             asm volatile("cp.async.wait_group 0;\n");
        __syncthreads();
        if (kt + 2 < KT) load_stage((kt + 2) % NSTAGE, kt + 2);

        uint32_t sA = sbase + (kt % NSTAGE) * STG_B;
        uint32_t sB = sA + 16384;
        #pragma unroll
        for (int kk = 0; kk < 64; kk += 16) {
            const int ck = kk >> 3;
            uint32_t af[4][4], bf[4][2];
            const int cA = ck + aCkL;
            #pragma unroll
            for (int rt = 0; rt < 4; rt++) {
                int r = wr0 + rt * 16 + aRowL;
                ldsm_x4(af[rt][0], af[rt][1], af[rt][2], af[rt][3],
                        sA + r * 128 + (((cA ^ r) & 7) << 4));
            }
            const int cB = ck + bCkL;
            #pragma unroll
            for (int p = 0; p < 2; p++) {
                int r = wc0 + p * 16 + bRowL;
                uint32_t m0, m1, m2, m3;
                ldsm_x4(m0, m1, m2, m3, sB + r * 128 + (((cB ^ r) & 7) << 4));
                bf[2*p][0] = m0; bf[2*p][1] = m1;
                bf[2*p+1][0] = m2; bf[2*p+1][1] = m3;
            }
            #pragma unroll
            for (int r = 0; r < 4; r++)
                #pragma unroll
                for (int c = 0; c < 4; c++)
                    mma16816(acc[r][c], af[r], bf[c]);
        }
        __syncthreads();
    }

    // ---- epilogue ----
    if (MODE == 4 && col0 >= DD && col0 < 2*DD) {
        // k columns: reduce sum of squares; k is never stored.
        const int head = (col0 - DD + wc0) >> 6;
        const int part = (wc0 >> 5) & 1;
        #pragma unroll
        for (int r = 0; r < 4; r++) {
            int row = row0 + wr0 + r*16 + lq;
            float s0 = 0.f, s1 = 0.f;
            #pragma unroll
            for (int c = 0; c < 4; c++) {
                int col = col0 + wc0 + c*8 + lr*2;
                float2 b2 = *reinterpret_cast<const float2*>(bias + col);
                float v0 = acc[r][c][0] + b2.x, v1 = acc[r][c][1] + b2.y;
                float v2 = acc[r][c][2] + b2.x, v3 = acc[r][c][3] + b2.y;
                s0 += v0*v0 + v1*v1;
                s1 += v2*v2 + v3*v3;
            }
            s0 += __shfl_xor_sync(0xffffffffu, s0, 1);
            s0 += __shfl_xor_sync(0xffffffffu, s0, 2);
            s1 += __shfl_xor_sync(0xffffffffu, s1, 1);
            s1 += __shfl_xor_sync(0xffffffffu, s1, 2);
            if (lr == 0) {
                g_ksq2[((size_t)row*HH + head)*2 + part]     = s0;
                g_ksq2[((size_t)(row+8)*HH + head)*2 + part] = s1;
            }
        }
    } else {
        const bool doSig = (ACT == 1) || (MODE == 4 && col0 < DD);
        #pragma unroll
        for (int r = 0; r < 4; r++) {
            int row = row0 + wr0 + r*16 + lq;
            #pragma unroll
            for (int c = 0; c < 4; c++) {
                int col = col0 + wc0 + c*8 + lr*2;
                float2 b2 = *reinterpret_cast<const float2*>(bias + col);
                float v0 = acc[r][c][0] + b2.x, v1 = acc[r][c][1] + b2.y;
                float v2 = acc[r][c][2] + b2.x, v3 = acc[r][c][3] + b2.y;
                if (doSig) {
                    v0 = 1.f/(1.f + __expf(-v0)); v1 = 1.f/(1.f + __expf(-v1));
                    v2 = 1.f/(1.f + __expf(-v2)); v3 = 1.f/(1.f + __expf(-v3));
                }
                if (MODE == 0) {
                    *reinterpret_cast<float2*>(C + (size_t)row*ldc + col)     = make_float2(v0, v1);
                    *reinterpret_cast<float2*>(C + (size_t)(row+8)*ldc + col) = make_float2(v2, v3);
                } else {
                    __half2 h0 = __floats2half2_rn(v0, v1);
                    __half2 h1 = __floats2half2_rn(v2, v3);
                    if (MODE == 3) {
                        *(uint32_t*)(g_wallT + (size_t)row*DD + col)     = *(uint32_t*)&h0;
                        *(uint32_t*)(g_wallT + (size_t)(row+8)*DD + col) = *(uint32_t*)&h1;
                    } else if (col0 < DD) {       // MODE 4: gate
                        *(uint32_t*)(g_gateh + (size_t)row*DD + col)     = *(uint32_t*)&h0;
                        *(uint32_t*)(g_gateh + (size_t)(row+8)*DD + col) = *(uint32_t*)&h1;
                    } else {                      // MODE 4: v
                        int cc = col - 2*DD;
                        *(uint32_t*)(g_vh + (size_t)row*DD + cc)     = *(uint32_t*)&h0;
                        *(uint32_t*)(g_vh + (size_t)(row+8)*DD + cc) = *(uint32_t*)&h1;
                    }
                }
            }
        }
    }
}

// ---------------- field[bh][d][n] = v * ||k|| -------------------------------
__global__ __launch_bounds__(256)
void field_kernel() {
    const int bh = blockIdx.y;
    const int b  = bh >> 4, h = bh & 15;
    const int n0 = blockIdx.x * 32;
    __shared__ float s_kmag[32];
    __shared__ float s_t[64][33];
    const int tid = threadIdx.x;
    if (tid < 32) {
        const float* kp = g_ksq2 + ((size_t)(b*NN + n0 + tid)*HH + h)*2;
        s_kmag[tid] = sqrtf(kp[0] + kp[1]);
    }
    __syncthreads();
    for (int idx = tid; idx < 2048; idx += 256) {
        int nl = idx >> 6, d = idx & 63;
        float v = __half2float(g_vh[(size_t)(b*NN + n0 + nl)*DD + h*HD + d]);
        s_t[d][nl] = v * s_kmag[nl];
    }
    __syncthreads();
    for (int idx = tid; idx < 2048; idx += 256) {
        int d = idx >> 5, nl = idx & 31;
        g_fieldh[((size_t)bh*HD + d)*NN + n0 + nl] = __float2half_rn(s_t[d][nl]);
    }
}

// ---------- pyramid: 24 merged taps, zero-padded, half2 pairs ---------------
#define PADH 3072
#define PADA 1024
__global__ __launch_bounds__(256)
void pyramid_kernel() {
    const int r = blockIdx.x;               // bh*64 + d
    const int h = (r >> 6) & 15;
    const __half* row_g = g_fieldh + (size_t)r * NN;
    __shared__ __align__(16) __half s_row[PADH + NN];
    __shared__ __align__(16) float  s_acc[PADA + NN];
    const int tid = threadIdx.x;

    for (int i = tid; i < PADH/8; i += 256)
        reinterpret_cast<uint4*>(s_row)[i] = make_uint4(0,0,0,0);
    for (int i = tid; i < PADA/4; i += 256)
        reinterpret_cast<float4*>(s_acc)[i] = make_float4(0.f,0.f,0.f,0.f);
    for (int i = tid; i < NN/8; i += 256)
        reinterpret_cast<uint4*>(s_row + PADH)[i] =
            reinterpret_cast<const uint4*>(row_g)[i];

    float c[NTAPS];
    #pragma unroll
    for (int t = 0; t < NTAPS; t++) c[t] = g_tapc[t*HH + h];
    const float sw0 = g_sw[0], sw1 = g_sw[1];
    __syncthreads();

    const __half2* rowp = reinterpret_cast<const __half2*>(s_row);
    constexpr int GT = 19;
    constexpr int gidx[GT] = {4,5,6,7,8,9,10,11,12,  14,15,16,17,18,19,20,21,22,23};
    constexpr int goff[GT] = {4,8,16,32,64,128,256,512,1024,  3,6,12,24,48,96,192,384,768,1536};

    for (int ip = tid; ip < NN/2; ip += 256) {
        const int base = PADH/2 + ip;
        float2 f0 = __half22float2(rowp[base]);
        float2 f1 = __half22float2(rowp[base-1]);
        float2 f2 = __half22float2(rowp[base-2]);
        float a0 = c[0]*f0.x + c[1]*f1.y + c[2]*f1.x + c[13]*f2.y + c[3]*f2.x;
        float a1 = c[0]*f0.y + c[1]*f0.x + c[2]*f1.y + c[13]*f1.x + c[3]*f2.y;
        #pragma unroll
        for (int t = 0; t < GT; t++) {
            float2 f = __half22float2(rowp[base - goff[t]]);
            a0 += c[gidx[t]]*f.x;
            a1 += c[gidx[t]]*f.y;
        }
        s_acc[PADA + 2*ip]     = a0;
        s_acc[PADA + 2*ip + 1] = a1;
    }
    __syncthreads();

    __half* out_g = g_acch + (size_t)r * NN;
    for (int ip = tid; ip < NN/2; ip += 256) {
        int n = 2*ip;
        float2 v  = *reinterpret_cast<float2*>(&s_acc[PADA + n]);
        float2 a  = *reinterpret_cast<float2*>(&s_acc[PADA + n - 512]);
        float2 b  = *reinterpret_cast<float2*>(&s_acc[PADA + n - 1024]);
        v.x += sw0*a.x + sw1*b.x;
        v.y += sw0*a.y + sw1*b.y;
        __half2 hv = __floats2half2_rn(v.x, v.y);
        *reinterpret_cast<uint32_t*>(out_g + n) = *reinterpret_cast<uint32_t*>(&hv);
    }
}

// ------- fused coupling + transpose-back + gate + half-convert --------------
#define CGP 1040
#define CGSMEM (HH*CGP*4)   // 66560 bytes
__global__ __launch_bounds__(256)
void cg_kernel() {
    extern __shared__ float s[];
    __shared__ float sc[HH*HH];
    const int b  = blockIdx.y;
    const int n0 = blockIdx.x * 16;
    const int tid = threadIdx.x;
    if (tid < HH*HH) sc[tid] = g_coup[tid];
    for (int idx = tid; idx < 2048; idx += 256) {
        int row = idx >> 1, c8 = idx & 1;
        int j = row >> 6, d = row & 63;
        uint4 u = *reinterpret_cast<const uint4*>(
            g_acch + ((size_t)(b*HH + j)*HD + d)*NN + n0 + c8*8);
        const __half2* hp = reinterpret_cast<const __half2*>(&u);
        float* sp = s + j*CGP + d;
        #pragma unroll
        for (int e = 0; e < 4; e++) {
            float2 f = __half22float2(hp[e]);
            sp[(c8*8 + e*2)*64]     = f.x;
            sp[(c8*8 + e*2 + 1)*64] = f.y;
        }
    }
    __syncthreads();
    #pragma unroll
    for (int t = 0; t < 4; t++) {
        int p  = tid + 256*t;
        int d  = p & 63, nl = p >> 6;
        float in[HH];
        #pragma unroll
        for (int j = 0; j < HH; j++) in[j] = s[j*CGP + nl*64 + d];
        #pragma unroll
        for (int h = 0; h < HH; h++) {
            float o = 0.f;
            #pragma unroll
            for (int j = 0; j < HH; j++) o += sc[h*HH + j] * in[j];
            size_t addr = ((size_t)(b*NN + n0 + nl))*DD + h*HD + d;
            float gt = __half2float(g_gateh[addr]);
            g_preh[addr] = __float2half_rn(o * gt);
        }
    }
}

// ---------------- launch ----------------------------------------------------
extern "C" void kernel_launch(void* const* d_in, const int* in_sizes, int n_in,
                              void* d_out, int out_size) {
    const float* x          = (const float*)d_in[0];
    const float* Wqkv       = (const float*)d_in[1];
    const float* bqkv       = (const float*)d_in[2];
    const float* Wout       = (const float*)d_in[3];
    const float* bout       = (const float*)d_in[4];
    const float* Wgate      = (const float*)d_in[5];
    const float* bgate      = (const float*)d_in[6];
    const float* scale_gain = (const float*)d_in[7];
    const float* skip_w     = (const float*)d_in[8];
    const float* coupling   = (const float*)d_in[9];
    float* out = (float*)d_out;

    __half *p_xh, *p_preh, *p_wallT, *p_wgateT, *p_woutT, *p_wqh;
    float *p_bias3, *p_zeros;
    cudaGetSymbolAddress((void**)&p_xh,     g_xh);
    cudaGetSymbolAddress((void**)&p_preh,   g_preh);
    cudaGetSymbolAddress((void**)&p_wallT,  g_wallT);
    cudaGetSymbolAddress((void**)&p_wgateT, g_wgateT);
    cudaGetSymbolAddress((void**)&p_woutT,  g_woutT);
    cudaGetSymbolAddress((void**)&p_wqh,    g_wqh);
    cudaGetSymbolAddress((void**)&p_bias3,  g_bias3);
    cudaGetSymbolAddress((void**)&p_zeros,  g_zeros);

    cudaFuncSetAttribute(mma_gemm<0,4>, cudaFuncAttributeMaxDynamicSharedMemorySize, GSMEM);
    cudaFuncSetAttribute(mma_gemm<0,0>, cudaFuncAttributeMaxDynamicSharedMemorySize, GSMEM);
    cudaFuncSetAttribute(mma_gemm<0,3>, cudaFuncAttributeMaxDynamicSharedMemorySize, GSMEM);
    cudaFuncSetAttribute(cg_kernel,     cudaFuncAttributeMaxDynamicSharedMemorySize, CGSMEM);

    prep_kernel<<<1, 32>>>(scale_gain, skip_w, coupling);
    bcomb1_kernel<<<dim3(DD/256, 32), 256>>>(bqkv, Wgate);
    bias3_kernel<<<N3D/256, 256>>>(bgate, bqkv);

    // kv weights -> rows 1024..3071 of g_wallT
    wtrans_kernel<<<dim3((2*DD)/32, DD/32), 256>>>(Wqkv + DD, p_wallT + (size_t)DD*DD, DD, N3D);
    wtrans_kernel<<<dim3(DD/32,  DD/32), 256>>>(Wgate, p_wgateT, DD, DD);
    wtrans_kernel<<<dim3(DD/32,  DD/32), 256>>>(Wout,  p_woutT,  DD, DD);
    qw_kernel<<<(DD*DD/4)/256, 256>>>(Wqkv);
    tohalf_kernel<<<(MTOT*DD/4)/256, 256>>>(x, p_xh);

    // WcombT = WgateT @ Wq^T -> rows 0..1023 of g_wallT
    mma_gemm<0,3><<<dim3(DD/128, DD/128), 256, GSMEM>>>(
        p_wgateT, p_wqh, p_zeros, nullptr, 0, DD);
    // merged GEMM: [gate | k-sumsq | v] = x @ [Wcomb | Wkv] + bias3
    mma_gemm<0,4><<<dim3(N3D/128, MTOT/128), 256, GSMEM>>>(
        p_xh, p_wallT, p_bias3, nullptr, 0, DD);

    field_kernel  <<<dim3(NN/32, BB*HH), 256>>>();
    pyramid_kernel<<<BB*HH*HD, 256>>>();
    cg_kernel     <<<dim3(NN/16, BB), 256, CGSMEM>>>();

    // out = pre @ Wout + bout
    mma_gemm<0,0><<<dim3(DD/128, MTOT/128), 256, GSMEM>>>(
        p_preh, p_woutT, bout, out, DD, DD);
}

// round 16
// speedup vs baseline: 1.1635x; 1.0263x over previous
#include <cuda_runtime.h>
#include <cuda_fp16.h>
#include <math.h>
#include <stdint.h>

// ---------------- problem constants ----------------
#define BB 4
#define NN 4096
#define DD 1024
#define HH 16
#define HD 64
#define MTOT (BB*NN)          // 16384
#define N3D (3*DD)            // 3072
#define NSCALES 11
#define NTAPS 24

#define C0 0.4829629131445341f
#define C1 0.8365163037378079f
#define C2 0.2241438680420134f
#define C3 (-0.1294095225512604f)

// ---------------- scratch (device globals; allocation-free) ----------------
__device__ __half g_xh    [(size_t)MTOT * DD];      // 32 MB
__device__ __half g_vt    [(size_t)BB*HH*HD*NN];    // 32 MB  v transposed [bh*64+d][n]
__device__ float  g_ksqT  [(size_t)BB*HH*2*NN];     // 4 MB   [(bh*2+part)][n]
__device__ float  g_kmagT [(size_t)BB*HH*NN];       // 2 MB   [bh][n]
__device__ __half g_gateh [(size_t)MTOT * DD];      // 32 MB
__device__ __half g_acch  [(size_t)BB*HH*HD*NN];    // 32 MB
__device__ __half g_preh  [(size_t)MTOT * DD];      // 32 MB
__device__ __half g_wallT [(size_t)N3D * DD];       // 6 MB: rows 0-1023 wcombT, 1024-3071 wkvT
__device__ __half g_wgateT[(size_t)DD * DD];
__device__ __half g_woutT [(size_t)DD * DD];
__device__ __half g_wqh   [(size_t)DD * DD];        // Wqkv[:, :1024] packed half
__device__ float  g_bcombP[32][DD];                 // bcomb partials
__device__ float  g_bias3 [N3D];                    // bcomb | bqkv[1024:3072]
__device__ float  g_zeros [DD];                     // zero-initialized, never written
__device__ float  g_gains [NSCALES*HH];
__device__ float  g_tapc  [NTAPS*HH];               // merged tap coefs per head
__device__ float  g_sw    [2];
__device__ float  g_coup  [HH*HH];

// ---------------- helpers ----------------
__device__ __forceinline__ void cpa16(uint32_t s, const void* g) {
    asm volatile("cp.async.cg.shared.global [%0], [%1], 16;\n" :: "r"(s), "l"(g));
}
__device__ __forceinline__ void mma16816(float* d, const uint32_t* a, const uint32_t* b) {
    asm volatile(
        "mma.sync.aligned.m16n8k16.row.col.f32.f16.f16.f32 "
        "{%0,%1,%2,%3}, {%4,%5,%6,%7}, {%8,%9}, {%0,%1,%2,%3};\n"
        : "+f"(d[0]), "+f"(d[1]), "+f"(d[2]), "+f"(d[3])
        : "r"(a[0]), "r"(a[1]), "r"(a[2]), "r"(a[3]), "r"(b[0]), "r"(b[1]));
}
__device__ __forceinline__ void ldsm_x4(uint32_t& r0, uint32_t& r1, uint32_t& r2, uint32_t& r3,
                                        uint32_t addr) {
    asm volatile("ldmatrix.sync.aligned.m8n8.x4.shared.b16 {%0,%1,%2,%3}, [%4];"
                 : "=r"(r0), "=r"(r1), "=r"(r2), "=r"(r3) : "r"(addr));
}

// ---------------- K0: tiny prep (+ merged tap coefficients) ----------------
__global__ void prep_kernel(const float* __restrict__ scale_gain,
                            const float* __restrict__ skip_w,
                            const float* __restrict__ coupling) {
    int t = threadIdx.x;
    if (t < HH) {
        float m = -1e30f;
        for (int j = 0; j < NSCALES; j++) m = fmaxf(m, scale_gain[j*HH + t]);
        float e[NSCALES]; float s = 0.f;
        for (int j = 0; j < NSCALES; j++) { e[j] = expf(scale_gain[j*HH + t] - m); s += e[j]; }
        float g[NSCALES];
        for (int j = 0; j < NSCALES; j++) { g[j] = e[j] / s; g_gains[j*HH + t] = g[j]; }
        g_tapc[0*HH + t] = C3;
        for (int j = 0; j <= 11; j++) {
            float c = 0.f;
            if (j <= 10) c += C2 * g[j];
            if (j >= 1)  c += C1 * g[j-1];
            g_tapc[(1+j)*HH + t] = c;
        }
        for (int j = 0; j <= 10; j++) g_tapc[(13+j)*HH + t] = C0 * g[j];

        float m2 = -1e30f;
        for (int j = 0; j < HH; j++) m2 = fmaxf(m2, coupling[t*HH + j]);
        float e2[HH]; float s2 = 0.f;
        for (int j = 0; j < HH; j++) { e2[j] = expf(coupling[t*HH + j] - m2); s2 += e2[j]; }
        for (int j = 0; j < HH; j++) g_coup[t*HH + j] = e2[j] / s2;
    }
    if (t < 2) g_sw[t] = 1.f / (1.f + expf(-skip_w[t]));
}

// ---- bcomb stage 1: coalesced partials ----
__global__ __launch_bounds__(256)
void bcomb1_kernel(const float* __restrict__ bqkv, const float* __restrict__ Wgate) {
    int j = blockIdx.x * 256 + threadIdx.x;
    int part = blockIdx.y;
    float s = 0.f;
    #pragma unroll 8
    for (int l = part*32; l < part*32 + 32; l++)
        s += bqkv[l] * Wgate[(size_t)l*DD + j];
    g_bcombP[part][j] = s;
}
// ---- bias3: j<DD -> bcomb; else copy bqkv[j] ----
__global__ __launch_bounds__(256)
void bias3_kernel(const float* __restrict__ bgate, const float* __restrict__ bqkv) {
    int j = blockIdx.x * 256 + threadIdx.x;
    if (j < DD) {
        float s = bgate[j];
        #pragma unroll
        for (int p = 0; p < 32; p++) s += g_bcombP[p][j];
        g_bias3[j] = s;
    } else {
        g_bias3[j] = bqkv[j];
    }
}

// ---------------- weight transpose to half: Wt[n][k] = (half)W[k][n] --------
__global__ __launch_bounds__(256)
void wtrans_kernel(const float* __restrict__ W, __half* __restrict__ Wt,
                   int K, int Nw) {
    __shared__ float s[32][33];
    int n0 = blockIdx.x * 32, k0 = blockIdx.y * 32;
    int tx = threadIdx.x & 31, ty = threadIdx.x >> 5;
    #pragma unroll
    for (int i = 0; i < 32; i += 8)
        s[ty + i][tx] = W[(size_t)(k0 + ty + i) * Nw + n0 + tx];
    __syncthreads();
    #pragma unroll
    for (int i = 0; i < 32; i += 8)
        Wt[(size_t)(n0 + ty + i) * K + k0 + tx] = __float2half_rn(s[tx][ty + i]);
}

// ---- pack Wqkv[:, :1024] to half row-major [i][l] ----
__global__ __launch_bounds__(256)
void qw_kernel(const float* __restrict__ Wqkv) {
    size_t idx = (size_t)blockIdx.x * 256 + threadIdx.x;
    int i = (int)(idx >> 8);
    int c = (int)(idx & 255);
    float4 v = *reinterpret_cast<const float4*>(Wqkv + (size_t)i*N3D + c*4);
    __half2 h01 = __floats2half2_rn(v.x, v.y);
    __half2 h23 = __floats2half2_rn(v.z, v.w);
    uint2 u = make_uint2(*(uint32_t*)&h01, *(uint32_t*)&h23);
    reinterpret_cast<uint2*>(g_wqh + (size_t)i*DD)[c] = u;
}

// ---------------- x -> half ----------------
__global__ __launch_bounds__(256)
void tohalf_kernel(const float* __restrict__ in, __half* __restrict__ out) {
    size_t i = (size_t)blockIdx.x * 256 + threadIdx.x;
    float4 v = reinterpret_cast<const float4*>(in)[i];
    __half2 h01 = __floats2half2_rn(v.x, v.y);
    __half2 h23 = __floats2half2_rn(v.z, v.w);
    uint2 u = make_uint2(*(uint32_t*)&h01, *(uint32_t*)&h23);
    reinterpret_cast<uint2*>(out)[i] = u;
}

// ---- kmag[bh][n] = sqrt(ksqT[bh][0][n] + ksqT[bh][1][n]) ----
__global__ __launch_bounds__(256)
void kmag_kernel() {
    const int bh = blockIdx.x;
    const float* k0 = g_ksqT + (size_t)(bh*2)*NN;
    const float* k1 = k0 + NN;
    float* out = g_kmagT + (size_t)bh*NN;
    for (int n = threadIdx.x; n < NN; n += 256)
        out[n] = sqrtf(k0[n] + k1[n]);
}

// ===== fp16 mma.sync GEMM with ldmatrix feeds: C = A[M,K] @ Bt[N,K]^T + bias
#define STG_B 32768
#define NSTAGE 3
#define GSMEM (NSTAGE*STG_B)   // 98304 bytes

// MODE 0: C fp32 (+sigmoid if ACT).
// MODE 3: half -> g_wallT (wcomb region, rows 0..1023).
// MODE 4: merged epilogue: col0<1024 -> sigmoid -> g_gateh;
//         1024..2047 -> k sum-of-squares partials (transposed);
//         >=2048 -> v transposed half into g_vt.
template<int ACT, int MODE>
__global__ __launch_bounds__(256)
void mma_gemm(const __half* __restrict__ A,
              const __half* __restrict__ Bt,
              const float* __restrict__ bias,
              float* __restrict__ C, int ldc, int K) {
    extern __shared__ char smem[];
    const int tid  = threadIdx.x;
    const int lane = tid & 31;
    const int warp = tid >> 5;
    const int row0 = blockIdx.y * 128;
    const int col0 = blockIdx.x * 128;
    const int wr0  = (warp >> 2) * 64;
    const int wc0  = (warp & 3) * 32;
    const int lq   = lane >> 2;
    const int lr   = lane & 3;

    uint32_t sbase;
    asm("{ .reg .u64 t; cvta.to.shared.u64 t, %1; cvt.u32.u64 %0, t; }"
        : "=r"(sbase) : "l"((const void*)smem));

    float acc[4][4][4];
    #pragma unroll
    for (int r = 0; r < 4; r++)
        #pragma unroll
        for (int c = 0; c < 4; c++)
            #pragma unroll
            for (int e = 0; e < 4; e++) acc[r][c][e] = 0.f;

    auto load_stage = [&](int s, int kt) {
        uint32_t abase = sbase + s * STG_B;
        uint32_t bbase = abase + 16384;
        #pragma unroll
        for (int i = 0; i < 4; i++) {
            int c = tid + i * 256;
            int r = c >> 3, cc = c & 7;
            cpa16(abase + r * 128 + (((cc ^ r) & 7) << 4),
                  A + (size_t)(row0 + r) * K + kt * 64 + cc * 8);
        }
        #pragma unroll
        for (int i = 0; i < 4; i++) {
            int c = tid + i * 256;
            int r = c >> 3, cc = c & 7;
            cpa16(bbase + r * 128 + (((cc ^ r) & 7) << 4),
                  Bt + (size_t)(col0 + r) * K + kt * 64 + cc * 8);
        }
        asm volatile("cp.async.commit_group;\n");
    };

    const int KT = K >> 6;
    load_stage(0, 0);
    load_stage(1, 1);

    const int aRowL = lane & 15;
    const int aCkL  = lane >> 4;
    const int bRowL = (lane & 7) + ((lane >> 4) << 3);
    const int bCkL  = (lane >> 3) & 1;

    for (int kt = 0; kt < KT; kt++) {
        if (kt + 1 < KT) asm volatile("cp.async.wait_group 1;\n");
        else             asm volatile("cp.async.wait_group 0;\n");
        __syncthreads();
        if (kt + 2 < KT) load_stage((kt + 2) % NSTAGE, kt + 2);

        uint32_t sA = sbase + (kt % NSTAGE) * STG_B;
        uint32_t sB = sA + 16384;
        #pragma unroll
        for (int kk = 0; kk < 64; kk += 16) {
            const int ck = kk >> 3;
            uint32_t af[4][4], bf[4][2];
            const int cA = ck + aCkL;
            #pragma unroll
            for (int rt = 0; rt < 4; rt++) {
                int r = wr0 + rt * 16 + aRowL;
                ldsm_x4(af[rt][0], af[rt][1], af[rt][2], af[rt][3],
                        sA + r * 128 + (((cA ^ r) & 7) << 4));
            }
            const int cB = ck + bCkL;
            #pragma unroll
            for (int p = 0; p < 2; p++) {
                int r = wc0 + p * 16 + bRowL;
                uint32_t m0, m1, m2, m3;
                ldsm_x4(m0, m1, m2, m3, sB + r * 128 + (((cB ^ r) & 7) << 4));
                bf[2*p][0] = m0; bf[2*p][1] = m1;
                bf[2*p+1][0] = m2; bf[2*p+1][1] = m3;
            }
            #pragma unroll
            for (int r = 0; r < 4; r++)
                #pragma unroll
                for (int c = 0; c < 4; c++)
                    mma16816(acc[r][c], af[r], bf[c]);
        }
        __syncthreads();
    }

    // ---- epilogue ----
    if (MODE == 4 && col0 >= DD && col0 < 2*DD) {
        // k columns: reduce sum of squares; store transposed [(bh*2+part)][n].
        const int head = (col0 - DD + wc0) >> 6;
        const int part = (wc0 >> 5) & 1;
        #pragma unroll
        for (int r = 0; r < 4; r++) {
            int row = row0 + wr0 + r*16 + lq;
            float s0 = 0.f, s1 = 0.f;
            #pragma unroll
            for (int c = 0; c < 4; c++) {
                int col = col0 + wc0 + c*8 + lr*2;
                float2 b2 = *reinterpret_cast<const float2*>(bias + col);
                float v0 = acc[r][c][0] + b2.x, v1 = acc[r][c][1] + b2.y;
                float v2 = acc[r][c][2] + b2.x, v3 = acc[r][c][3] + b2.y;
                s0 += v0*v0 + v1*v1;
                s1 += v2*v2 + v3*v3;
            }
            s0 += __shfl_xor_sync(0xffffffffu, s0, 1);
            s0 += __shfl_xor_sync(0xffffffffu, s0, 2);
            s1 += __shfl_xor_sync(0xffffffffu, s1, 1);
            s1 += __shfl_xor_sync(0xffffffffu, s1, 2);
            if (lr == 0) {
                int b = row >> 12, n = row & (NN-1);
                float* kp = g_ksqT + ((size_t)(b*HH + head)*2 + part)*NN;
                kp[n]     = s0;
                kp[n + 8] = s1;
            }
        }
    } else {
        const bool doSig = (ACT == 1) || (MODE == 4 && col0 < DD);
        #pragma unroll
        for (int r = 0; r < 4; r++) {
            int row = row0 + wr0 + r*16 + lq;
            #pragma unroll
            for (int c = 0; c < 4; c++) {
                int col = col0 + wc0 + c*8 + lr*2;
                float2 b2 = *reinterpret_cast<const float2*>(bias + col);
                float v0 = acc[r][c][0] + b2.x, v1 = acc[r][c][1] + b2.y;
                float v2 = acc[r][c][2] + b2.x, v3 = acc[r][c][3] + b2.y;
                if (doSig) {
                    v0 = 1.f/(1.f + __expf(-v0)); v1 = 1.f/(1.f + __expf(-v1));
                    v2 = 1.f/(1.f + __expf(-v2)); v3 = 1.f/(1.f + __expf(-v3));
                }
                if (MODE == 0) {
                    *reinterpret_cast<float2*>(C + (size_t)row*ldc + col)     = make_float2(v0, v1);
                    *reinterpret_cast<float2*>(C + (size_t)(row+8)*ldc + col) = make_float2(v2, v3);
                } else if (MODE == 3) {
                    __half2 h0 = __floats2half2_rn(v0, v1);
                    __half2 h1 = __floats2half2_rn(v2, v3);
                    *(uint32_t*)(g_wallT + (size_t)row*DD + col)     = *(uint32_t*)&h0;
                    *(uint32_t*)(g_wallT + (size_t)(row+8)*DD + col) = *(uint32_t*)&h1;
                } else if (col0 < DD) {       // MODE 4: gate
                    __half2 h0 = __floats2half2_rn(v0, v1);
                    __half2 h1 = __floats2half2_rn(v2, v3);
                    *(uint32_t*)(g_gateh + (size_t)row*DD + col)     = *(uint32_t*)&h0;
                    *(uint32_t*)(g_gateh + (size_t)(row+8)*DD + col) = *(uint32_t*)&h1;
                } else {                      // MODE 4: v transposed
                    int b = row >> 12, n = row & (NN-1);
                    int cc = col - 2*DD;      // h*64 + d
                    __half* vp0 = g_vt + ((size_t)(b*HH + (cc>>6))*HD + (cc&63))*NN;
                    __half* vp1 = vp0 + NN;   // d+1 row
                    vp0[n]     = __float2half_rn(v0);
                    vp1[n]     = __float2half_rn(v1);
                    vp0[n + 8] = __float2half_rn(v2);
                    vp1[n + 8] = __float2half_rn(v3);
                }
            }
        }
    }
}

// ---------- pyramid: v*kmag on load, 24 merged taps, half2 pairs ------------
#define PADH 3072
#define PADA 1024
__global__ __launch_bounds__(256)
void pyramid_kernel() {
    const int r = blockIdx.x;               // bh*64 + d
    const int h = (r >> 6) & 15;
    const __half* vrow = g_vt + (size_t)r * NN;
    const float* krow  = g_kmagT + (size_t)(r >> 6) * NN;
    __shared__ __align__(16) __half s_row[PADH + NN];
    __shared__ __align__(16) float  s_acc[PADA + NN];
    const int tid = threadIdx.x;

    for (int i = tid; i < PADH/8; i += 256)
        reinterpret_cast<uint4*>(s_row)[i] = make_uint4(0,0,0,0);
    for (int i = tid; i < PADA/4; i += 256)
        reinterpret_cast<float4*>(s_acc)[i] = make_float4(0.f,0.f,0.f,0.f);
    // field = v * kmag, rounded to half (same rounding point as before)
    for (int i = tid; i < NN/8; i += 256) {
        uint4 u = reinterpret_cast<const uint4*>(vrow)[i];
        const __half2* hp = reinterpret_cast<const __half2*>(&u);
        float4 ka = reinterpret_cast<const float4*>(krow)[2*i];
        float4 kb = reinterpret_cast<const float4*>(krow)[2*i+1];
        uint4 o;
        __half2* op = reinterpret_cast<__half2*>(&o);
        float2 f;
        f = __half22float2(hp[0]); op[0] = __floats2half2_rn(f.x*ka.x, f.y*ka.y);
        f = __half22float2(hp[1]); op[1] = __floats2half2_rn(f.x*ka.z, f.y*ka.w);
        f = __half22float2(hp[2]); op[2] = __floats2half2_rn(f.x*kb.x, f.y*kb.y);
        f = __half22float2(hp[3]); op[3] = __floats2half2_rn(f.x*kb.z, f.y*kb.w);
        reinterpret_cast<uint4*>(s_row + PADH)[i] = o;
    }

    float c[NTAPS];
    #pragma unroll
    for (int t = 0; t < NTAPS; t++) c[t] = g_tapc[t*HH + h];
    const float sw0 = g_sw[0], sw1 = g_sw[1];
    __syncthreads();

    const __half2* rowp = reinterpret_cast<const __half2*>(s_row);
    constexpr int GT = 19;
    constexpr int gidx[GT] = {4,5,6,7,8,9,10,11,12,  14,15,16,17,18,19,20,21,22,23};
    constexpr int goff[GT] = {4,8,16,32,64,128,256,512,1024,  3,6,12,24,48,96,192,384,768,1536};

    for (int ip = tid; ip < NN/2; ip += 256) {
        const int base = PADH/2 + ip;
        float2 f0 = __half22float2(rowp[base]);
        float2 f1 = __half22float2(rowp[base-1]);
        float2 f2 = __half22float2(rowp[base-2]);
        float a0 = c[0]*f0.x + c[1]*f1.y + c[2]*f1.x + c[13]*f2.y + c[3]*f2.x;
        float a1 = c[0]*f0.y + c[1]*f0.x + c[2]*f1.y + c[13]*f1.x + c[3]*f2.y;
        #pragma unroll
        for (int t = 0; t < GT; t++) {
            float2 f = __half22float2(rowp[base - goff[t]]);
            a0 += c[gidx[t]]*f.x;
            a1 += c[gidx[t]]*f.y;
        }
        s_acc[PADA + 2*ip]     = a0;
        s_acc[PADA + 2*ip + 1] = a1;
    }
    __syncthreads();

    __half* out_g = g_acch + (size_t)r * NN;
    for (int ip = tid; ip < NN/2; ip += 256) {
        int n = 2*ip;
        float2 v  = *reinterpret_cast<float2*>(&s_acc[PADA + n]);
        float2 a  = *reinterpret_cast<float2*>(&s_acc[PADA + n - 512]);
        float2 b  = *reinterpret_cast<float2*>(&s_acc[PADA + n - 1024]);
        v.x += sw0*a.x + sw1*b.x;
        v.y += sw0*a.y + sw1*b.y;
        __half2 hv = __floats2half2_rn(v.x, v.y);
        *reinterpret_cast<uint32_t*>(out_g + n) = *reinterpret_cast<uint32_t*>(&hv);
    }
}

// ------- fused coupling + transpose-back + gate + half-convert --------------
#define CGP 1040
#define CGSMEM (HH*CGP*4)   // 66560 bytes
__global__ __launch_bounds__(256)
void cg_kernel() {
    extern __shared__ float s[];
    __shared__ float sc[HH*HH];
    const int b  = blockIdx.y;
    const int n0 = blockIdx.x * 16;
    const int tid = threadIdx.x;
    if (tid < HH*HH) sc[tid] = g_coup[tid];
    for (int idx = tid; idx < 2048; idx += 256) {
        int row = idx >> 1, c8 = idx & 1;
        int j = row >> 6, d = row & 63;
        uint4 u = *reinterpret_cast<const uint4*>(
            g_acch + ((size_t)(b*HH + j)*HD + d)*NN + n0 + c8*8);
        const __half2* hp = reinterpret_cast<const __half2*>(&u);
        float* sp = s + j*CGP + d;
        #pragma unroll
        for (int e = 0; e < 4; e++) {
            float2 f = __half22float2(hp[e]);
            sp[(c8*8 + e*2)*64]     = f.x;
            sp[(c8*8 + e*2 + 1)*64] = f.y;
        }
    }
    __syncthreads();
    #pragma unroll
    for (int t = 0; t < 4; t++) {
        int p  = tid + 256*t;
        int d  = p & 63, nl = p >> 6;
        float in[HH];
        #pragma unroll
        for (int j = 0; j < HH; j++) in[j] = s[j*CGP + nl*64 + d];
        #pragma unroll
        for (int h = 0; h < HH; h++) {
            float o = 0.f;
            #pragma unroll
            for (int j = 0; j < HH; j++) o += sc[h*HH + j] * in[j];
            size_t addr = ((size_t)(b*NN + n0 + nl))*DD + h*HD + d;
            float gt = __half2float(g_gateh[addr]);
            g_preh[addr] = __float2half_rn(o * gt);
        }
    }
}

// ---------------- launch ----------------------------------------------------
extern "C" void kernel_launch(void* const* d_in, const int* in_sizes, int n_in,
                              void* d_out, int out_size) {
    const float* x          = (const float*)d_in[0];
    const float* Wqkv       = (const float*)d_in[1];
    const float* bqkv       = (const float*)d_in[2];
    const float* Wout       = (const float*)d_in[3];
    const float* bout       = (const float*)d_in[4];
    const float* Wgate      = (const float*)d_in[5];
    const float* bgate      = (const float*)d_in[6];
    const float* scale_gain = (const float*)d_in[7];
    const float* skip_w     = (const float*)d_in[8];
    const float* coupling   = (const float*)d_in[9];
    float* out = (float*)d_out;

    __half *p_xh, *p_preh, *p_wallT, *p_wgateT, *p_woutT, *p_wqh;
    float *p_bias3, *p_zeros;
    cudaGetSymbolAddress((void**)&p_xh,     g_xh);
    cudaGetSymbolAddress((void**)&p_preh,   g_preh);
    cudaGetSymbolAddress((void**)&p_wallT,  g_wallT);
    cudaGetSymbolAddress((void**)&p_wgateT, g_wgateT);
    cudaGetSymbolAddress((void**)&p_woutT,  g_woutT);
    cudaGetSymbolAddress((void**)&p_wqh,    g_wqh);
    cudaGetSymbolAddress((void**)&p_bias3,  g_bias3);
    cudaGetSymbolAddress((void**)&p_zeros,  g_zeros);

    cudaFuncSetAttribute(mma_gemm<0,4>, cudaFuncAttributeMaxDynamicSharedMemorySize, GSMEM);
    cudaFuncSetAttribute(mma_gemm<0,0>, cudaFuncAttributeMaxDynamicSharedMemorySize, GSMEM);
    cudaFuncSetAttribute(mma_gemm<0,3>, cudaFuncAttributeMaxDynamicSharedMemorySize, GSMEM);
    cudaFuncSetAttribute(cg_kernel,     cudaFuncAttributeMaxDynamicSharedMemorySize, CGSMEM);

    prep_kernel<<<1, 32>>>(scale_gain, skip_w, coupling);
    bcomb1_kernel<<<dim3(DD/256, 32), 256>>>(bqkv, Wgate);
    bias3_kernel<<<N3D/256, 256>>>(bgate, bqkv);

    // kv weights -> rows 1024..3071 of g_wallT
    wtrans_kernel<<<dim3((2*DD)/32, DD/32), 256>>>(Wqkv + DD, p_wallT + (size_t)DD*DD, DD, N3D);
    wtrans_kernel<<<dim3(DD/32,  DD/32), 256>>>(Wgate, p_wgateT, DD, DD);
    wtrans_kernel<<<dim3(DD/32,  DD/32), 256>>>(Wout,  p_woutT,  DD, DD);
    qw_kernel<<<(DD*DD/4)/256, 256>>>(Wqkv);
    tohalf_kernel<<<(MTOT*DD/4)/256, 256>>>(x, p_xh);

    // WcombT = WgateT @ Wq^T -> rows 0..1023 of g_wallT
    mma_gemm<0,3><<<dim3(DD/128, DD/128), 256, GSMEM>>>(
        p_wgateT, p_wqh, p_zeros, nullptr, 0, DD);
    // merged GEMM: [gate | k-sumsq(T) | v(T)] = x @ [Wcomb | Wkv] + bias3
    mma_gemm<0,4><<<dim3(N3D/128, MTOT/128), 256, GSMEM>>>(
        p_xh, p_wallT, p_bias3, nullptr, 0, DD);

    kmag_kernel   <<<BB*HH, 256>>>();
    pyramid_kernel<<<BB*HH*HD, 256>>>();
    cg_kernel     <<<dim3(NN/16, BB), 256, CGSMEM>>>();

    // out = pre @ Wout + bout
    mma_gemm<0,0><<<dim3(DD/128, MTOT/128), 256, GSMEM>>>(
        p_preh, p_woutT, bout, out, DD, DD);
}

// round 17
// speedup vs baseline: 1.8394x; 1.5809x over previous
#include <cuda_runtime.h>
#include <cuda_fp16.h>
#include <math.h>
#include <stdint.h>

// ---------------- problem constants ----------------
#define BB 4
#define NN 4096
#define DD 1024
#define HH 16
#define HD 64
#define MTOT (BB*NN)          // 16384
#define N3D (3*DD)            // 3072
#define NSCALES 11
#define NTAPS 24

#define C0 0.4829629131445341f
#define C1 0.8365163037378079f
#define C2 0.2241438680420134f
#define C3 (-0.1294095225512604f)

// ---------------- scratch (device globals; allocation-free) ----------------
__device__ __half g_xh    [(size_t)MTOT * DD];      // 32 MB
__device__ __half g_vt    [(size_t)BB*HH*HD*NN];    // 32 MB  v transposed [bh*64+d][n]
__device__ float  g_ksqT  [(size_t)BB*HH*2*NN];     // 4 MB   [(bh*2+part)][n]
__device__ float  g_kmagT [(size_t)BB*HH*NN];       // 2 MB   [bh][n]
__device__ __half g_gateh [(size_t)MTOT * DD];      // 32 MB
__device__ __half g_acch  [(size_t)BB*HH*HD*NN];    // 32 MB
__device__ __half g_preh  [(size_t)MTOT * DD];      // 32 MB
__device__ __half g_wallT [(size_t)N3D * DD];       // 6 MB: rows 0-1023 wcombT, 1024-3071 wkvT
__device__ __half g_wgateT[(size_t)DD * DD];
__device__ __half g_woutT [(size_t)DD * DD];
__device__ __half g_wqh   [(size_t)DD * DD];        // Wqkv[:, :1024] packed half
__device__ float  g_bcombP[32][DD];                 // bcomb partials
__device__ float  g_bias3 [N3D];                    // bcomb | bqkv[1024:3072]
__device__ float  g_zeros [DD];                     // zero-initialized, never written
__device__ float  g_gains [NSCALES*HH];
__device__ float  g_tapc  [NTAPS*HH];               // merged tap coefs per head
__device__ float  g_sw    [2];
__device__ float  g_coup  [HH*HH];

// ---------------- helpers ----------------
__device__ __forceinline__ void cpa16(uint32_t s, const void* g) {
    asm volatile("cp.async.cg.shared.global [%0], [%1], 16;\n" :: "r"(s), "l"(g));
}
__device__ __forceinline__ void mma16816(float* d, const uint32_t* a, const uint32_t* b) {
    asm volatile(
        "mma.sync.aligned.m16n8k16.row.col.f32.f16.f16.f32 "
        "{%0,%1,%2,%3}, {%4,%5,%6,%7}, {%8,%9}, {%0,%1,%2,%3};\n"
        : "+f"(d[0]), "+f"(d[1]), "+f"(d[2]), "+f"(d[3])
        : "r"(a[0]), "r"(a[1]), "r"(a[2]), "r"(a[3]), "r"(b[0]), "r"(b[1]));
}
__device__ __forceinline__ void ldsm_x4(uint32_t& r0, uint32_t& r1, uint32_t& r2, uint32_t& r3,
                                        uint32_t addr) {
    asm volatile("ldmatrix.sync.aligned.m8n8.x4.shared.b16 {%0,%1,%2,%3}, [%4];"
                 : "=r"(r0), "=r"(r1), "=r"(r2), "=r"(r3) : "r"(addr));
}

// ---------------- K0: tiny prep (+ merged tap coefficients) ----------------
__global__ void prep_kernel(const float* __restrict__ scale_gain,
                            const float* __restrict__ skip_w,
                            const float* __restrict__ coupling) {
    int t = threadIdx.x;
    if (t < HH) {
        float m = -1e30f;
        for (int j = 0; j < NSCALES; j++) m = fmaxf(m, scale_gain[j*HH + t]);
        float e[NSCALES]; float s = 0.f;
        for (int j = 0; j < NSCALES; j++) { e[j] = expf(scale_gain[j*HH + t] - m); s += e[j]; }
        float g[NSCALES];
        for (int j = 0; j < NSCALES; j++) { g[j] = e[j] / s; g_gains[j*HH + t] = g[j]; }
        g_tapc[0*HH + t] = C3;
        for (int j = 0; j <= 11; j++) {
            float c = 0.f;
            if (j <= 10) c += C2 * g[j];
            if (j >= 1)  c += C1 * g[j-1];
            g_tapc[(1+j)*HH + t] = c;
        }
        for (int j = 0; j <= 10; j++) g_tapc[(13+j)*HH + t] = C0 * g[j];

        float m2 = -1e30f;
        for (int j = 0; j < HH; j++) m2 = fmaxf(m2, coupling[t*HH + j]);
        float e2[HH]; float s2 = 0.f;
        for (int j = 0; j < HH; j++) { e2[j] = expf(coupling[t*HH + j] - m2); s2 += e2[j]; }
        for (int j = 0; j < HH; j++) g_coup[t*HH + j] = e2[j] / s2;
    }
    if (t < 2) g_sw[t] = 1.f / (1.f + expf(-skip_w[t]));
}

// ---- bcomb stage 1: coalesced partials ----
__global__ __launch_bounds__(256)
void bcomb1_kernel(const float* __restrict__ bqkv, const float* __restrict__ Wgate) {
    int j = blockIdx.x * 256 + threadIdx.x;
    int part = blockIdx.y;
    float s = 0.f;
    #pragma unroll 8
    for (int l = part*32; l < part*32 + 32; l++)
        s += bqkv[l] * Wgate[(size_t)l*DD + j];
    g_bcombP[part][j] = s;
}
// ---- bias3: j<DD -> bcomb; else copy bqkv[j] ----
__global__ __launch_bounds__(256)
void bias3_kernel(const float* __restrict__ bgate, const float* __restrict__ bqkv) {
    int j = blockIdx.x * 256 + threadIdx.x;
    if (j < DD) {
        float s = bgate[j];
        #pragma unroll
        for (int p = 0; p < 32; p++) s += g_bcombP[p][j];
        g_bias3[j] = s;
    } else {
        g_bias3[j] = bqkv[j];
    }
}

// ---------------- weight transpose to half: Wt[n][k] = (half)W[k][n] --------
__global__ __launch_bounds__(256)
void wtrans_kernel(const float* __restrict__ W, __half* __restrict__ Wt,
                   int K, int Nw) {
    __shared__ float s[32][33];
    int n0 = blockIdx.x * 32, k0 = blockIdx.y * 32;
    int tx = threadIdx.x & 31, ty = threadIdx.x >> 5;
    #pragma unroll
    for (int i = 0; i < 32; i += 8)
        s[ty + i][tx] = W[(size_t)(k0 + ty + i) * Nw + n0 + tx];
    __syncthreads();
    #pragma unroll
    for (int i = 0; i < 32; i += 8)
        Wt[(size_t)(n0 + ty + i) * K + k0 + tx] = __float2half_rn(s[tx][ty + i]);
}

// ---- pack Wqkv[:, :1024] to half row-major [i][l] ----
__global__ __launch_bounds__(256)
void qw_kernel(const float* __restrict__ Wqkv) {
    size_t idx = (size_t)blockIdx.x * 256 + threadIdx.x;
    int i = (int)(idx >> 8);
    int c = (int)(idx & 255);
    float4 v = *reinterpret_cast<const float4*>(Wqkv + (size_t)i*N3D + c*4);
    __half2 h01 = __floats2half2_rn(v.x, v.y);
    __half2 h23 = __floats2half2_rn(v.z, v.w);
    uint2 u = make_uint2(*(uint32_t*)&h01, *(uint32_t*)&h23);
    reinterpret_cast<uint2*>(g_wqh + (size_t)i*DD)[c] = u;
}

// ---------------- x -> half ----------------
__global__ __launch_bounds__(256)
void tohalf_kernel(const float* __restrict__ in, __half* __restrict__ out) {
    size_t i = (size_t)blockIdx.x * 256 + threadIdx.x;
    float4 v = reinterpret_cast<const float4*>(in)[i];
    __half2 h01 = __floats2half2_rn(v.x, v.y);
    __half2 h23 = __floats2half2_rn(v.z, v.w);
    uint2 u = make_uint2(*(uint32_t*)&h01, *(uint32_t*)&h23);
    reinterpret_cast<uint2*>(out)[i] = u;
}

// ---- kmag[bh][n] = sqrt(ksqT[bh][0][n] + ksqT[bh][1][n]) ----
__global__ __launch_bounds__(256)
void kmag_kernel() {
    const int bh = blockIdx.x;
    const float* k0 = g_ksqT + (size_t)(bh*2)*NN;
    const float* k1 = k0 + NN;
    float* out = g_kmagT + (size_t)bh*NN;
    for (int n = threadIdx.x; n < NN; n += 256)
        out[n] = sqrtf(k0[n] + k1[n]);
}

// ===== fp16 mma.sync GEMM with ldmatrix feeds: C = A[M,K] @ Bt[N,K]^T + bias
#define STG_B 32768
#define NSTAGE 3
#define GSMEM (NSTAGE*STG_B)   // 98304 bytes

// MODE 0: C fp32 (+sigmoid if ACT).
// MODE 3: half -> g_wallT (wcomb region, rows 0..1023).
// MODE 4: merged epilogue: col0<1024 -> sigmoid -> g_gateh;
//         1024..2047 -> k sum-of-squares partials (transposed);
//         >=2048 -> v transposed half into g_vt.
template<int ACT, int MODE>
__global__ __launch_bounds__(256)
void mma_gemm(const __half* __restrict__ A,
              const __half* __restrict__ Bt,
              const float* __restrict__ bias,
              float* __restrict__ C, int ldc, int K) {
    extern __shared__ char smem[];
    const int tid  = threadIdx.x;
    const int lane = tid & 31;
    const int warp = tid >> 5;
    const int row0 = blockIdx.y * 128;
    const int col0 = blockIdx.x * 128;
    const int wr0  = (warp >> 2) * 64;
    const int wc0  = (warp & 3) * 32;
    const int lq   = lane >> 2;
    const int lr   = lane & 3;

    uint32_t sbase;
    asm("{ .reg .u64 t; cvta.to.shared.u64 t, %1; cvt.u32.u64 %0, t; }"
        : "=r"(sbase) : "l"((const void*)smem));

    float acc[4][4][4];
    #pragma unroll
    for (int r = 0; r < 4; r++)
        #pragma unroll
        for (int c = 0; c < 4; c++)
            #pragma unroll
            for (int e = 0; e < 4; e++) acc[r][c][e] = 0.f;

    auto load_stage = [&](int s, int kt) {
        uint32_t abase = sbase + s * STG_B;
        uint32_t bbase = abase + 16384;
        #pragma unroll
        for (int i = 0; i < 4; i++) {
            int c = tid + i * 256;
            int r = c >> 3, cc = c & 7;
            cpa16(abase + r * 128 + (((cc ^ r) & 7) << 4),
                  A + (size_t)(row0 + r) * K + kt * 64 + cc * 8);
        }
        #pragma unroll
        for (int i = 0; i < 4; i++) {
            int c = tid + i * 256;
            int r = c >> 3, cc = c & 7;
            cpa16(bbase + r * 128 + (((cc ^ r) & 7) << 4),
                  Bt + (size_t)(col0 + r) * K + kt * 64 + cc * 8);
        }
        asm volatile("cp.async.commit_group;\n");
    };

    const int KT = K >> 6;
    load_stage(0, 0);
    load_stage(1, 1);

    const int aRowL = lane & 15;
    const int aCkL  = lane >> 4;
    const int bRowL = (lane & 7) + ((lane >> 4) << 3);
    const int bCkL  = (lane >> 3) & 1;

    for (int kt = 0; kt < KT; kt++) {
        if (kt + 1 < KT) asm volatile("cp.async.wait_group 1;\n");
        else             asm volatile("cp.async.wait_group 0;\n");
        __syncthreads();
        if (kt + 2 < KT) load_stage((kt + 2) % NSTAGE, kt + 2);

        uint32_t sA = sbase + (kt % NSTAGE) * STG_B;
        uint32_t sB = sA + 16384;
        #pragma unroll
        for (int kk = 0; kk < 64; kk += 16) {
            const int ck = kk >> 3;
            uint32_t af[4][4], bf[4][2];
            const int cA = ck + aCkL;
            #pragma unroll
            for (int rt = 0; rt < 4; rt++) {
                int r = wr0 + rt * 16 + aRowL;
                ldsm_x4(af[rt][0], af[rt][1], af[rt][2], af[rt][3],
                        sA + r * 128 + (((cA ^ r) & 7) << 4));
            }
            const int cB = ck + bCkL;
            #pragma unroll
            for (int p = 0; p < 2; p++) {
                int r = wc0 + p * 16 + bRowL;
                uint32_t m0, m1, m2, m3;
                ldsm_x4(m0, m1, m2, m3, sB + r * 128 + (((cB ^ r) & 7) << 4));
                bf[2*p][0] = m0; bf[2*p][1] = m1;
                bf[2*p+1][0] = m2; bf[2*p+1][1] = m3;
            }
            #pragma unroll
            for (int r = 0; r < 4; r++)
                #pragma unroll
                for (int c = 0; c < 4; c++)
                    mma16816(acc[r][c], af[r], bf[c]);
        }
        __syncthreads();
    }

    // ---- epilogue ----
    if (MODE == 4 && col0 >= DD && col0 < 2*DD) {
        const int head = (col0 - DD + wc0) >> 6;
        const int part = (wc0 >> 5) & 1;
        #pragma unroll
        for (int r = 0; r < 4; r++) {
            int row = row0 + wr0 + r*16 + lq;
            float s0 = 0.f, s1 = 0.f;
            #pragma unroll
            for (int c = 0; c < 4; c++) {
                int col = col0 + wc0 + c*8 + lr*2;
                float2 b2 = *reinterpret_cast<const float2*>(bias + col);
                float v0 = acc[r][c][0] + b2.x, v1 = acc[r][c][1] + b2.y;
                float v2 = acc[r][c][2] + b2.x, v3 = acc[r][c][3] + b2.y;
                s0 += v0*v0 + v1*v1;
                s1 += v2*v2 + v3*v3;
            }
            s0 += __shfl_xor_sync(0xffffffffu, s0, 1);
            s0 += __shfl_xor_sync(0xffffffffu, s0, 2);
            s1 += __shfl_xor_sync(0xffffffffu, s1, 1);
            s1 += __shfl_xor_sync(0xffffffffu, s1, 2);
            if (lr == 0) {
                int b = row >> 12, n = row & (NN-1);
                float* kp = g_ksqT + ((size_t)(b*HH + head)*2 + part)*NN;
                kp[n]     = s0;
                kp[n + 8] = s1;
            }
        }
    } else {
        const bool doSig = (ACT == 1) || (MODE == 4 && col0 < DD);
        #pragma unroll
        for (int r = 0; r < 4; r++) {
            int row = row0 + wr0 + r*16 + lq;
            #pragma unroll
            for (int c = 0; c < 4; c++) {
                int col = col0 + wc0 + c*8 + lr*2;
                float2 b2 = *reinterpret_cast<const float2*>(bias + col);
                float v0 = acc[r][c][0] + b2.x, v1 = acc[r][c][1] + b2.y;
                float v2 = acc[r][c][2] + b2.x, v3 = acc[r][c][3] + b2.y;
                if (doSig) {
                    v0 = 1.f/(1.f + __expf(-v0)); v1 = 1.f/(1.f + __expf(-v1));
                    v2 = 1.f/(1.f + __expf(-v2)); v3 = 1.f/(1.f + __expf(-v3));
                }
                if (MODE == 0) {
                    *reinterpret_cast<float2*>(C + (size_t)row*ldc + col)     = make_float2(v0, v1);
                    *reinterpret_cast<float2*>(C + (size_t)(row+8)*ldc + col) = make_float2(v2, v3);
                } else if (MODE == 3) {
                    __half2 h0 = __floats2half2_rn(v0, v1);
                    __half2 h1 = __floats2half2_rn(v2, v3);
                    *(uint32_t*)(g_wallT + (size_t)row*DD + col)     = *(uint32_t*)&h0;
                    *(uint32_t*)(g_wallT + (size_t)(row+8)*DD + col) = *(uint32_t*)&h1;
                } else if (col0 < DD) {       // MODE 4: gate
                    __half2 h0 = __floats2half2_rn(v0, v1);
                    __half2 h1 = __floats2half2_rn(v2, v3);
                    *(uint32_t*)(g_gateh + (size_t)row*DD + col)     = *(uint32_t*)&h0;
                    *(uint32_t*)(g_gateh + (size_t)(row+8)*DD + col) = *(uint32_t*)&h1;
                } else {                      // MODE 4: v transposed
                    int b = row >> 12, n = row & (NN-1);
                    int cc = col - 2*DD;      // h*64 + d
                    __half* vp0 = g_vt + ((size_t)(b*HH + (cc>>6))*HD + (cc&63))*NN;
                    __half* vp1 = vp0 + NN;
                    vp0[n]     = __float2half_rn(v0);
                    vp1[n]     = __float2half_rn(v1);
                    vp0[n + 8] = __float2half_rn(v2);
                    vp1[n + 8] = __float2half_rn(v3);
                }
            }
        }
    }
}

// ---------- pyramid: v*kmag on load, 24 merged taps, quad outputs -----------
#define PADH 3072
#define PADA 1024
__global__ __launch_bounds__(256)
void pyramid_kernel() {
    const int r = blockIdx.x;               // bh*64 + d
    const int h = (r >> 6) & 15;
    const __half* vrow = g_vt + (size_t)r * NN;
    const float* krow  = g_kmagT + (size_t)(r >> 6) * NN;
    __shared__ __align__(16) __half s_row[PADH + NN];
    __shared__ __align__(16) float  s_acc[PADA + NN];
    const int tid = threadIdx.x;

    for (int i = tid; i < PADH/8; i += 256)
        reinterpret_cast<uint4*>(s_row)[i] = make_uint4(0,0,0,0);
    for (int i = tid; i < PADA/4; i += 256)
        reinterpret_cast<float4*>(s_acc)[i] = make_float4(0.f,0.f,0.f,0.f);
    // field = v * kmag, rounded to half (same rounding point as before)
    for (int i = tid; i < NN/8; i += 256) {
        uint4 u = reinterpret_cast<const uint4*>(vrow)[i];
        const __half2* hp = reinterpret_cast<const __half2*>(&u);
        float4 ka = reinterpret_cast<const float4*>(krow)[2*i];
        float4 kb = reinterpret_cast<const float4*>(krow)[2*i+1];
        uint4 o;
        __half2* op = reinterpret_cast<__half2*>(&o);
        float2 f;
        f = __half22float2(hp[0]); op[0] = __floats2half2_rn(f.x*ka.x, f.y*ka.y);
        f = __half22float2(hp[1]); op[1] = __floats2half2_rn(f.x*ka.z, f.y*ka.w);
        f = __half22float2(hp[2]); op[2] = __floats2half2_rn(f.x*kb.x, f.y*kb.y);
        f = __half22float2(hp[3]); op[3] = __floats2half2_rn(f.x*kb.z, f.y*kb.w);
        reinterpret_cast<uint4*>(s_row + PADH)[i] = o;
    }

    float c[NTAPS];
    #pragma unroll
    for (int t = 0; t < NTAPS; t++) c[t] = g_tapc[t*HH + h];
    const float sw0 = g_sw[0], sw1 = g_sw[1];
    __syncthreads();

    const __half2* rowp = reinterpret_cast<const __half2*>(s_row);
    // even-h2-offset generic taps (18): coef index + half2 offset
    constexpr int GT = 18;
    constexpr int gci[GT] = {4,5,6,7,8,9,10,11,12, 15,16,17,18,19,20,21,22,23};
    constexpr int gho[GT] = {4,8,16,32,64,128,256,512,1024, 6,12,24,48,96,192,384,768,1536};

    for (int iq = tid; iq < NN/4; iq += 256) {
        const int base2 = PADH/2 + 2*iq;      // h2 idx of x[n0q], even
        // near window x[n0q-6 .. n0q+3]
        uint2 um = *reinterpret_cast<const uint2*>(&rowp[base2-2]); // x[-4..-1]
        uint2 u0 = *reinterpret_cast<const uint2*>(&rowp[base2]);   // x[0..3]
        __half2 h6 = rowp[base2-3];                                 // x[-6],x[-5]
        float xv[10];
        { float2 f = __half22float2(h6);                 xv[0]=f.x; xv[1]=f.y; }
        { float2 f = __half22float2(*(__half2*)&um.x);   xv[2]=f.x; xv[3]=f.y; }
        { float2 f = __half22float2(*(__half2*)&um.y);   xv[4]=f.x; xv[5]=f.y; }
        { float2 f = __half22float2(*(__half2*)&u0.x);   xv[6]=f.x; xv[7]=f.y; }
        { float2 f = __half22float2(*(__half2*)&u0.y);   xv[8]=f.x; xv[9]=f.y; }
        float y[4];
        #pragma unroll
        for (int m = 0; m < 4; m++) {
            y[m] = c[0]*xv[6+m] + c[1]*xv[5+m] + c[2]*xv[4+m]
                 + c[13]*xv[3+m] + c[3]*xv[2+m] + c[14]*xv[m];
        }
        #pragma unroll
        for (int t = 0; t < GT; t++) {
            uint2 u = *reinterpret_cast<const uint2*>(&rowp[base2 - gho[t]]);
            float2 fa = __half22float2(*(__half2*)&u.x);
            float2 fb = __half22float2(*(__half2*)&u.y);
            float cf = c[gci[t]];
            y[0] += cf*fa.x; y[1] += cf*fa.y; y[2] += cf*fb.x; y[3] += cf*fb.y;
        }
        *reinterpret_cast<float4*>(&s_acc[PADA + 4*iq]) = make_float4(y[0],y[1],y[2],y[3]);
    }
    __syncthreads();

    __half* out_g = g_acch + (size_t)r * NN;
    for (int iq = tid; iq < NN/4; iq += 256) {
        int n = 4*iq;
        float4 v = *reinterpret_cast<float4*>(&s_acc[PADA + n]);
        float4 a = *reinterpret_cast<float4*>(&s_acc[PADA + n - 512]);
        float4 b = *reinterpret_cast<float4*>(&s_acc[PADA + n - 1024]);
        v.x += sw0*a.x + sw1*b.x;
        v.y += sw0*a.y + sw1*b.y;
        v.z += sw0*a.z + sw1*b.z;
        v.w += sw0*a.w + sw1*b.w;
        __half2 h0 = __floats2half2_rn(v.x, v.y);
        __half2 h1 = __floats2half2_rn(v.z, v.w);
        uint2 o = make_uint2(*(uint32_t*)&h0, *(uint32_t*)&h1);
        *reinterpret_cast<uint2*>(out_g + n) = o;
    }
}

// ------- fused coupling + transpose-back + gate, d-pair vectorized ----------
#define CGP 1040
#define CGSMEM (HH*CGP*4)   // 66560 bytes
__global__ __launch_bounds__(256)
void cg_kernel() {
    extern __shared__ float s[];
    __shared__ float sc[HH*HH];
    const int b  = blockIdx.y;
    const int n0 = blockIdx.x * 16;
    const int tid = threadIdx.x;
    if (tid < HH*HH) sc[tid] = g_coup[tid];
    for (int idx = tid; idx < 2048; idx += 256) {
        int row = idx >> 1, c8 = idx & 1;
        int j = row >> 6, d = row & 63;
        uint4 u = *reinterpret_cast<const uint4*>(
            g_acch + ((size_t)(b*HH + j)*HD + d)*NN + n0 + c8*8);
        const __half2* hp = reinterpret_cast<const __half2*>(&u);
        float* sp = s + j*CGP + d;
        #pragma unroll
        for (int e = 0; e < 4; e++) {
            float2 f = __half22float2(hp[e]);
            sp[(c8*8 + e*2)*64]     = f.x;
            sp[(c8*8 + e*2 + 1)*64] = f.y;
        }
    }
    __syncthreads();
    #pragma unroll
    for (int t = 0; t < 2; t++) {
        int p  = tid + 256*t;       // nl*32 + d2
        int d  = (p & 31) * 2, nl = p >> 5;
        float2 in[HH];
        #pragma unroll
        for (int j = 0; j < HH; j++)
            in[j] = *reinterpret_cast<const float2*>(&s[j*CGP + nl*64 + d]);
        size_t rowbase = ((size_t)(b*NN + n0 + nl))*DD;
        #pragma unroll
        for (int h = 0; h < HH; h++) {
            float ox = 0.f, oy = 0.f;
            #pragma unroll
            for (int j = 0; j < HH; j++) {
                float cj = sc[h*HH + j];
                ox += cj * in[j].x;
                oy += cj * in[j].y;
            }
            size_t addr = rowbase + h*HD + d;
            __half2 gt2 = *reinterpret_cast<const __half2*>(&g_gateh[addr]);
            float2 gf = __half22float2(gt2);
            __half2 hv = __floats2half2_rn(ox * gf.x, oy * gf.y);
            *reinterpret_cast<__half2*>(&g_preh[addr]) = hv;
        }
    }
}

// ---------------- launch ----------------------------------------------------
extern "C" void kernel_launch(void* const* d_in, const int* in_sizes, int n_in,
                              void* d_out, int out_size) {
    const float* x          = (const float*)d_in[0];
    const float* Wqkv       = (const float*)d_in[1];
    const float* bqkv       = (const float*)d_in[2];
    const float* Wout       = (const float*)d_in[3];
    const float* bout       = (const float*)d_in[4];
    const float* Wgate      = (const float*)d_in[5];
    const float* bgate      = (const float*)d_in[6];
    const float* scale_gain = (const float*)d_in[7];
    const float* skip_w     = (const float*)d_in[8];
    const float* coupling   = (const float*)d_in[9];
    float* out = (float*)d_out;

    __half *p_xh, *p_preh, *p_wallT, *p_wgateT, *p_woutT, *p_wqh;
    float *p_bias3, *p_zeros;
    cudaGetSymbolAddress((void**)&p_xh,     g_xh);
    cudaGetSymbolAddress((void**)&p_preh,   g_preh);
    cudaGetSymbolAddress((void**)&p_wallT,  g_wallT);
    cudaGetSymbolAddress((void**)&p_wgateT, g_wgateT);
    cudaGetSymbolAddress((void**)&p_woutT,  g_woutT);
    cudaGetSymbolAddress((void**)&p_wqh,    g_wqh);
    cudaGetSymbolAddress((void**)&p_bias3,  g_bias3);
    cudaGetSymbolAddress((void**)&p_zeros,  g_zeros);

    cudaFuncSetAttribute(mma_gemm<0,4>, cudaFuncAttributeMaxDynamicSharedMemorySize, GSMEM);
    cudaFuncSetAttribute(mma_gemm<0,0>, cudaFuncAttributeMaxDynamicSharedMemorySize, GSMEM);
    cudaFuncSetAttribute(mma_gemm<0,3>, cudaFuncAttributeMaxDynamicSharedMemorySize, GSMEM);
    cudaFuncSetAttribute(cg_kernel,     cudaFuncAttributeMaxDynamicSharedMemorySize, CGSMEM);

    prep_kernel<<<1, 32>>>(scale_gain, skip_w, coupling);
    bcomb1_kernel<<<dim3(DD/256, 32), 256>>>(bqkv, Wgate);
    bias3_kernel<<<N3D/256, 256>>>(bgate, bqkv);

    wtrans_kernel<<<dim3((2*DD)/32, DD/32), 256>>>(Wqkv + DD, p_wallT + (size_t)DD*DD, DD, N3D);
    wtrans_kernel<<<dim3(DD/32,  DD/32), 256>>>(Wgate, p_wgateT, DD, DD);
    wtrans_kernel<<<dim3(DD/32,  DD/32), 256>>>(Wout,  p_woutT,  DD, DD);
    qw_kernel<<<(DD*DD/4)/256, 256>>>(Wqkv);
    tohalf_kernel<<<(MTOT*DD/4)/256, 256>>>(x, p_xh);

    // WcombT = WgateT @ Wq^T -> rows 0..1023 of g_wallT
    mma_gemm<0,3><<<dim3(DD/128, DD/128), 256, GSMEM>>>(
        p_wgateT, p_wqh, p_zeros, nullptr, 0, DD);
    // merged GEMM: [gate | k-sumsq(T) | v(T)] = x @ [Wcomb | Wkv] + bias3
    mma_gemm<0,4><<<dim3(N3D/128, MTOT/128), 256, GSMEM>>>(
        p_xh, p_wallT, p_bias3, nullptr, 0, DD);

    kmag_kernel   <<<BB*HH, 256>>>();
    pyramid_kernel<<<BB*HH*HD, 256>>>();
    cg_kernel     <<<dim3(NN/16, BB), 256, CGSMEM>>>();

    // out = pre @ Wout + bout
    mma_gemm<0,0><<<dim3(DD/128, MTOT/128), 256, GSMEM>>>(
        p_preh, p_woutT, bout, out, DD, DD);
}